// round 12
// baseline (speedup 1.0000x reference)
#include <cuda_runtime.h>
#include <cuda_fp16.h>
#include <math.h>
#include <stdint.h>

#define SEQ   1024
#define BATCH 2
#define HID   768
#define NHEAD 12
#define HDIM  64
#define FFD   3072
#define MTOT  (BATCH*SEQ)   // 2048
#define BHTOT (BATCH*NHEAD) // 24

#define APAD 136
#define BPAD 72
#define HPAD 24   // halves per row (16 data + 8 pad) = 48B = 12 banks -> conflict-free

// ---------------- scratch (device globals: no allocation allowed) ----------------
__device__ float g_x [MTOT*HID];
__device__ float g_q [MTOT*HID];
__device__ float g_k [MTOT*HID];
__device__ float g_v [MTOT*HID];
__device__ float g_ao[MTOT*HID];
__device__ float g_r1[MTOT*HID];
__device__ float g_y [MTOT*HID];   // hosts softmax stats before ln2 reuses it
__device__ float g_ff[MTOT*FFD];

// stats offsets inside g_y (floats). 24576 rows, 16 tiles each.
#define PS_OFF   0
#define GI_OFF   (BHTOT*SEQ*16)

// ---------------- helpers ----------------
__device__ __forceinline__ unsigned long long f2add(unsigned long long a, unsigned long long b) {
    unsigned long long r;
    asm("add.rn.f32x2 %0, %1, %2;" : "=l"(r) : "l"(a), "l"(b));
    return r;
}

__device__ __forceinline__ float gelu1(float v) {
    return 0.5f * v * (1.f + erff(v * 0.70710678118654752f));
}

__device__ __forceinline__ float to_tf32(float x) {
    uint32_t u;
    asm("cvt.rna.tf32.f32 %0, %1;" : "=r"(u) : "f"(x));
    return __uint_as_float(u);
}

__device__ __forceinline__ void mma_tf32(float (&c)[4], const uint32_t (&a)[4],
                                         uint32_t b0, uint32_t b1) {
    asm("mma.sync.aligned.m16n8k8.row.col.f32.tf32.tf32.f32 "
        "{%0,%1,%2,%3}, {%4,%5,%6,%7}, {%8,%9}, {%0,%1,%2,%3};"
        : "+f"(c[0]), "+f"(c[1]), "+f"(c[2]), "+f"(c[3])
        : "r"(a[0]), "r"(a[1]), "r"(a[2]), "r"(a[3]), "r"(b0), "r"(b1));
}

__device__ __forceinline__ void mma_f16(float (&c)[4],
                                        uint32_t a0, uint32_t a1, uint32_t a2, uint32_t a3,
                                        uint32_t b0, uint32_t b1) {
    asm("mma.sync.aligned.m16n8k16.row.col.f32.f16.f16.f32 "
        "{%0,%1,%2,%3}, {%4,%5,%6,%7}, {%8,%9}, {%0,%1,%2,%3};"
        : "+f"(c[0]), "+f"(c[1]), "+f"(c[2]), "+f"(c[3])
        : "r"(a0), "r"(a1), "r"(a2), "r"(a3), "r"(b0), "r"(b1));
}

__device__ __forceinline__ uint32_t h2u(__half2 h) { return *(uint32_t*)&h; }

// ---------------- LayerNorm: one block per row of 768 ----------------
__global__ void ln_kernel(const float* __restrict__ in, const float* __restrict__ g,
                          const float* __restrict__ b, float* __restrict__ out) {
    int row = blockIdx.x;
    const float* x = in + (size_t)row * HID;
    int t = threadIdx.x;
    float v0 = x[t], v1 = x[t + 256], v2 = x[t + 512];
    float s  = v0 + v1 + v2;
    float sq = v0 * v0 + v1 * v1 + v2 * v2;
    __shared__ float sh[16];
    #pragma unroll
    for (int o = 16; o; o >>= 1) {
        s  += __shfl_xor_sync(0xffffffffu, s,  o);
        sq += __shfl_xor_sync(0xffffffffu, sq, o);
    }
    int w = t >> 5, l = t & 31;
    if (!l) { sh[w] = s; sh[w + 8] = sq; }
    __syncthreads();
    if (w == 0) {
        float a = (l < 8) ? sh[l] : 0.f;
        float c = (l < 8) ? sh[l + 8] : 0.f;
        #pragma unroll
        for (int o = 4; o; o >>= 1) {
            a += __shfl_xor_sync(0xffffffffu, a, o);
            c += __shfl_xor_sync(0xffffffffu, c, o);
        }
        if (!l) { sh[0] = a; sh[1] = c; }
    }
    __syncthreads();
    float mean = sh[0] * (1.f / HID);
    float var  = sh[1] * (1.f / HID) - mean * mean;
    float rs   = rsqrtf(var + 1e-5f);
    float* o = out + (size_t)row * HID;
    o[t]       = (v0 - mean) * rs * g[t]       + b[t];
    o[t + 256] = (v1 - mean) * rs * g[t + 256] + b[t + 256];
    o[t + 512] = (v2 - mean) * rs * g[t + 512] + b[t + 512];
}

// ======================= fp16 128x128 engine (qkv / Wo / FF) =======================
// As_h[m][k], Bs_h[n][k]; k-major rows of 16 halves padded to 24 (12 banks): fragment
// loads hit banks (gid*12+tig) mod 32 = all distinct -> conflict-free.
__device__ __forceinline__ void mma_compute_h(
    const __half (*Ab)[HPAD], const __half (*Bb)[HPAD],
    int m_base, int n_base, int gid, int tig, float (&acc)[4][4][4])
{
    int k0 = 2 * tig, k1 = 2 * tig + 8;
    uint32_t a[4][4];
    #pragma unroll
    for (int mf = 0; mf < 4; mf++) {
        int m0 = m_base + mf * 16 + gid;
        a[mf][0] = *(const uint32_t*)&Ab[m0][k0];
        a[mf][1] = *(const uint32_t*)&Ab[m0 + 8][k0];
        a[mf][2] = *(const uint32_t*)&Ab[m0][k1];
        a[mf][3] = *(const uint32_t*)&Ab[m0 + 8][k1];
    }
    #pragma unroll
    for (int nf = 0; nf < 4; nf++) {
        int n0 = n_base + nf * 8 + gid;
        uint32_t b0 = *(const uint32_t*)&Bb[n0][k0];
        uint32_t b1 = *(const uint32_t*)&Bb[n0][k1];
        #pragma unroll
        for (int mf = 0; mf < 4; mf++)
            mma_f16(acc[mf][nf], a[mf][0], a[mf][1], a[mf][2], a[mf][3], b0, b1);
    }
}

__device__ __forceinline__ void stage_A_h(__half (*As)[HPAD], int ar, int ac,
                                          float4 av0, float4 av1) {
    __half2 h0 = __floats2half2_rn(av0.x, av0.y);
    __half2 h1 = __floats2half2_rn(av0.z, av0.w);
    __half2 h2 = __floats2half2_rn(av1.x, av1.y);
    __half2 h3 = __floats2half2_rn(av1.z, av1.w);
    uint4 pk = make_uint4(h2u(h0), h2u(h1), h2u(h2), h2u(h3));
    *(uint4*)&As[ar][ac] = pk;   // ar*48 + ac*2 bytes: 16B aligned (ac in {0,8})
}

__device__ __forceinline__ void stage_B_h(__half (*Bs)[HPAD], int br, int bc,
                                          float4 bv0, float4 bv1) {
    Bs[bc + 0][br]  = __float2half_rn(bv0.x);
    Bs[bc + 1][br]  = __float2half_rn(bv0.y);
    Bs[bc + 2][br]  = __float2half_rn(bv0.z);
    Bs[bc + 3][br]  = __float2half_rn(bv0.w);
    Bs[bc + 64][br] = __float2half_rn(bv1.x);
    Bs[bc + 65][br] = __float2half_rn(bv1.y);
    Bs[bc + 66][br] = __float2half_rn(bv1.z);
    Bs[bc + 67][br] = __float2half_rn(bv1.w);
}

__device__ __forceinline__ void mma_tile_h(
    const float* __restrict__ A, int lda,
    const float* __restrict__ B, int ldb,
    int kLen,
    __half (*As)[128][HPAD], __half (*Bs)[128][HPAD],
    float (&acc)[4][4][4])
{
    int tid = threadIdx.x;
    int ar = tid >> 1, ac = (tid & 1) * 8;
    int br = tid >> 4, bc = (tid & 15) * 4;
    int lane = tid & 31, wid = tid >> 5;
    int gid = lane >> 2, tig = lane & 3;
    int m_base = (wid & 1) * 64, n_base = (wid >> 1) * 32;

    const float* Ap = A + (size_t)ar * lda + ac;
    const float* Bp = B + (size_t)br * ldb + bc;

    {
        float4 av0 = *(const float4*)(Ap);
        float4 av1 = *(const float4*)(Ap + 4);
        float4 bv0 = *(const float4*)(Bp);
        float4 bv1 = *(const float4*)(Bp + 64);
        stage_A_h(As[0], ar, ac, av0, av1);
        stage_B_h(Bs[0], br, bc, bv0, bv1);
    }
    __syncthreads();

    int kc = kLen >> 4;
    for (int c = 1; c < kc; c++) {
        const float* Ac = Ap + c * 16;
        const float* Bc = Bp + (size_t)(c * 16) * ldb;
        float4 av0 = *(const float4*)(Ac);
        float4 av1 = *(const float4*)(Ac + 4);
        float4 bv0 = *(const float4*)(Bc);
        float4 bv1 = *(const float4*)(Bc + 64);
        int pb = (c - 1) & 1, nb = c & 1;
        mma_compute_h(As[pb], Bs[pb], m_base, n_base, gid, tig, acc);
        stage_A_h(As[nb], ar, ac, av0, av1);
        stage_B_h(Bs[nb], br, bc, bv0, bv1);
        __syncthreads();
    }
    mma_compute_h(As[(kc - 1) & 1], Bs[(kc - 1) & 1], m_base, n_base, gid, tig, acc);
}

// ---------------- fused QKV: grid (18,16); blockIdx.x/6 selects matrix ----------------
__global__ void __launch_bounds__(256, 2) qkv_kernel(
    const float* __restrict__ x,
    const float* __restrict__ Wq, const float* __restrict__ Wk, const float* __restrict__ Wv,
    const float* __restrict__ bq, const float* __restrict__ bk, const float* __restrict__ bv,
    float* __restrict__ q, float* __restrict__ k, float* __restrict__ v)
{
    __shared__ __align__(16) __half As[2][128][HPAD];
    __shared__ __align__(16) __half Bs[2][128][HPAD];
    int sel = blockIdx.x / 6;
    int bn  = (blockIdx.x % 6) * 128;
    int bm  = blockIdx.y * 128;
    const float* B    = sel == 0 ? Wq : (sel == 1 ? Wk : Wv);
    const float* bias = sel == 0 ? bq : (sel == 1 ? bk : bv);
    float* C          = sel == 0 ? q  : (sel == 1 ? k  : v);
    float acc[4][4][4] = {};
    mma_tile_h(x + (size_t)bm * HID, HID, B + bn, HID, HID, As, Bs, acc);
    int tid = threadIdx.x, lane = tid & 31, wid = tid >> 5;
    int gid = lane >> 2, tig = lane & 3;
    int m_base = (wid & 1) * 64, n_base = (wid >> 1) * 32;
    #pragma unroll
    for (int mf = 0; mf < 4; mf++) {
        int r0 = bm + m_base + mf * 16 + gid;
        #pragma unroll
        for (int nf = 0; nf < 4; nf++) {
            int col = bn + n_base + nf * 8 + tig * 2;
            float2 bi = *(const float2*)(bias + col);
            *(float2*)(C + (size_t)r0 * HID + col) =
                make_float2(acc[mf][nf][0] + bi.x, acc[mf][nf][1] + bi.y);
            *(float2*)(C + (size_t)(r0 + 8) * HID + col) =
                make_float2(acc[mf][nf][2] + bi.x, acc[mf][nf][3] + bi.y);
        }
    }
}

// ---------------- generic gemm: grid (N/128, M/128); mode 0=+bias 2=gelu(+bias) ----------------
__global__ void __launch_bounds__(256, 2) gemm_kernel(
    const float* __restrict__ A, int K,
    const float* __restrict__ B, int N,
    const float* __restrict__ bias,
    float* __restrict__ C, int mode)
{
    __shared__ __align__(16) __half As[2][128][HPAD];
    __shared__ __align__(16) __half Bs[2][128][HPAD];
    int bm = blockIdx.y * 128, bn = blockIdx.x * 128;
    float acc[4][4][4] = {};
    mma_tile_h(A + (size_t)bm * K, K, B + bn, N, K, As, Bs, acc);
    int tid = threadIdx.x, lane = tid & 31, wid = tid >> 5;
    int gid = lane >> 2, tig = lane & 3;
    int m_base = (wid & 1) * 64, n_base = (wid >> 1) * 32;
    #pragma unroll
    for (int mf = 0; mf < 4; mf++) {
        int r0 = bm + m_base + mf * 16 + gid;
        #pragma unroll
        for (int nf = 0; nf < 4; nf++) {
            int col = bn + n_base + nf * 8 + tig * 2;
            float2 bi = *(const float2*)(bias + col);
            float o0 = acc[mf][nf][0] + bi.x, o1 = acc[mf][nf][1] + bi.y;
            float o2 = acc[mf][nf][2] + bi.x, o3 = acc[mf][nf][3] + bi.y;
            if (mode == 2) { o0 = gelu1(o0); o1 = gelu1(o1); o2 = gelu1(o2); o3 = gelu1(o3); }
            *(float2*)(C + (size_t)r0 * N + col)       = make_float2(o0, o1);
            *(float2*)(C + (size_t)(r0 + 8) * N + col) = make_float2(o2, o3);
        }
    }
}

// ---------------- split-K=2 gemm: grid (N/128, M/128, 2) -> raw partials ----------------
__global__ void __launch_bounds__(256, 2) gemm_split_kernel(
    const float* __restrict__ A, int K,
    const float* __restrict__ B, int N,
    float* __restrict__ P1, float* __restrict__ P2)
{
    __shared__ __align__(16) __half As[2][128][HPAD];
    __shared__ __align__(16) __half Bs[2][128][HPAD];
    int bm = blockIdx.y * 128, bn = blockIdx.x * 128;
    int half_k = K >> 1, z = blockIdx.z;
    float acc[4][4][4] = {};
    mma_tile_h(A + (size_t)bm * K + z * half_k, K,
               B + (size_t)(z * half_k) * N + bn, N, half_k, As, Bs, acc);
    float* C = z ? P2 : P1;
    int tid = threadIdx.x, lane = tid & 31, wid = tid >> 5;
    int gid = lane >> 2, tig = lane & 3;
    int m_base = (wid & 1) * 64, n_base = (wid >> 1) * 32;
    #pragma unroll
    for (int mf = 0; mf < 4; mf++) {
        int r0 = bm + m_base + mf * 16 + gid;
        #pragma unroll
        for (int nf = 0; nf < 4; nf++) {
            int col = bn + n_base + nf * 8 + tig * 2;
            *(float2*)(C + (size_t)r0 * N + col)       = make_float2(acc[mf][nf][0], acc[mf][nf][1]);
            *(float2*)(C + (size_t)(r0 + 8) * N + col) = make_float2(acc[mf][nf][2], acc[mf][nf][3]);
        }
    }
}

// ---------------- epilogue: out = p1 + p2 + bias + res ----------------
__global__ void epi_kernel(const float* __restrict__ p1, const float* __restrict__ p2,
                           const float* __restrict__ bias, const float* __restrict__ res,
                           float* __restrict__ out)
{
    int idx = (blockIdx.x * 256 + threadIdx.x) * 4;
    int col = idx % HID;
    float4 a  = *(const float4*)(p1 + idx);
    float4 b  = *(const float4*)(p2 + idx);
    float4 r  = *(const float4*)(res + idx);
    float4 bi = *(const float4*)(bias + col);
    float4 o = make_float4(a.x + b.x + r.x + bi.x, a.y + b.y + r.y + bi.y,
                           a.z + b.z + r.z + bi.z, a.w + b.w + r.w + bi.w);
    *(float4*)(out + idx) = o;
}

// ---------------- L1 distance -> exp(score) + per-tile row sums ----------------
__global__ void __launch_bounds__(256) dist_kernel(
    const float* __restrict__ Q, const float* __restrict__ Km,
    const float* __restrict__ lamp, float* __restrict__ attn,
    float* __restrict__ pS)
{
    __shared__ unsigned long long Qs[32][128];   // [d-pair][q-row]
    __shared__ unsigned long long Ks[32][64];    // negated K
    int bh = blockIdx.z, b = bh / NHEAD, h = bh - b * NHEAD;
    int qbase = blockIdx.y * 128, kbase = blockIdx.x * 64;
    const float* Qb = Q  + (size_t)b * SEQ * HID + h * HDIM + (size_t)qbase * HID;
    const float* Kb = Km + (size_t)b * SEQ * HID + h * HDIM + (size_t)kbase * HID;
    int tid = threadIdx.x;

    union F2U { float2 f; unsigned long long u; };
    {
        int row = tid >> 1, hh = (tid & 1) * 32;
        #pragma unroll
        for (int i = 0; i < 8; i++) {
            float4 qv = *(const float4*)(Qb + (size_t)row * HID + hh + i * 4);
            F2U t;
            t.f = make_float2(qv.x, qv.y); Qs[(hh >> 1) + i * 2][row]     = t.u;
            t.f = make_float2(qv.z, qv.w); Qs[(hh >> 1) + i * 2 + 1][row] = t.u;
        }
    }
    {
        int row = tid >> 2, kq = (tid & 3) * 16;
        #pragma unroll
        for (int i = 0; i < 4; i++) {
            float4 kv = *(const float4*)(Kb + (size_t)row * HID + kq + i * 4);
            F2U t;
            t.f = make_float2(-kv.x, -kv.y); Ks[(kq >> 1) + i * 2][row]     = t.u;
            t.f = make_float2(-kv.z, -kv.w); Ks[(kq >> 1) + i * 2 + 1][row] = t.u;
        }
    }
    __syncthreads();

    int tx = tid & 15, ty = tid >> 4;
    int qs = ty * 8, ks = tx * 4;
    unsigned long long acc[8][4] = {};
    const unsigned long long MASK = 0x7FFFFFFF7FFFFFFFull;
    #pragma unroll 4
    for (int d = 0; d < 32; d++) {
        unsigned long long qv[8], kv[4];
        *(ulonglong2*)&qv[0] = *(const ulonglong2*)&Qs[d][qs];
        *(ulonglong2*)&qv[2] = *(const ulonglong2*)&Qs[d][qs + 2];
        *(ulonglong2*)&qv[4] = *(const ulonglong2*)&Qs[d][qs + 4];
        *(ulonglong2*)&qv[6] = *(const ulonglong2*)&Qs[d][qs + 6];
        *(ulonglong2*)&kv[0] = *(const ulonglong2*)&Ks[d][ks];
        *(ulonglong2*)&kv[2] = *(const ulonglong2*)&Ks[d][ks + 2];
        #pragma unroll
        for (int i = 0; i < 8; i++)
            #pragma unroll
            for (int j = 0; j < 4; j++) {
                unsigned long long df = f2add(qv[i], kv[j]) & MASK;
                acc[i][j] = f2add(acc[i][j], df);
            }
    }
    float c = -(*lamp) * 0.125f;   // scale = 1/sqrt(64)
    float* outp = attn + (size_t)bh * SEQ * SEQ + (size_t)(qbase + qs) * SEQ + kbase + ks;
    size_t srow = ((size_t)bh * SEQ + qbase + qs) * 16 + blockIdx.x;
    #pragma unroll
    for (int i = 0; i < 8; i++) {
        F2U t;
        float e0, e1, e2, e3;
        t.u = acc[i][0]; e0 = __expf(c * (t.f.x + t.f.y));
        t.u = acc[i][1]; e1 = __expf(c * (t.f.x + t.f.y));
        t.u = acc[i][2]; e2 = __expf(c * (t.f.x + t.f.y));
        t.u = acc[i][3]; e3 = __expf(c * (t.f.x + t.f.y));
        *(float4*)(outp + (size_t)i * SEQ) = make_float4(e0, e1, e2, e3);
        float s = e0 + e1 + e2 + e3;
        #pragma unroll
        for (int o = 8; o; o >>= 1) s += __shfl_xor_sync(0xffffffffu, s, o);
        if (tx == 0) pS[srow + (size_t)i * 16] = s;
    }
}

// ---------------- fold 16 tile-sums per row -> 1/sum ----------------
__global__ void stats_reduce(const float* __restrict__ pS, float* __restrict__ gI)
{
    int row = blockIdx.x * 256 + threadIdx.x;   // < 24576
    const float* s16 = pS + (size_t)row * 16;
    float s = 0.f;
    #pragma unroll
    for (int j = 0; j < 16; j += 4) {
        float4 a = *(const float4*)(s16 + j);
        s += a.x + a.y + a.z + a.w;
    }
    gI[row] = 1.f / s;
}

// ---------------- fused normalize + attn write + attn@V: grid (8,1,24) ----------------
__global__ void __launch_bounds__(256, 2) pv_kernel(
    float* __restrict__ attn, const float* __restrict__ V,
    const float* __restrict__ gI, float* __restrict__ O)
{
    __shared__ float As[2][16][APAD];
    __shared__ float Bs[2][16][BPAD];
    __shared__ float smI[128];
    int bh = blockIdx.z, b = bh / NHEAD, h = bh - b * NHEAD;
    int bm = blockIdx.x * 128;
    float* A        = attn + (size_t)bh * SEQ * SEQ + (size_t)bm * SEQ;
    const float* Bv = V + (size_t)b * SEQ * HID + h * HDIM;
    int tid = threadIdx.x;
    if (tid < 128) smI[tid] = gI[(size_t)bh * SEQ + bm + tid];
    __syncthreads();

    int ar = tid >> 1, ac = (tid & 1) * 8;
    int br = tid >> 4, bc = (tid & 15) * 4;
    int lane = tid & 31, wid = tid >> 5;
    int gid = lane >> 2, tig = lane & 3;
    int m_base = (wid & 3) * 32, n_base = (wid >> 2) * 32;
    float rowI = smI[ar];
    float acc[2][4][4] = {};

    float* Ap       = A + (size_t)ar * SEQ + ac;
    const float* Bp = Bv + (size_t)br * HID + bc;

    {
        float4 a0 = *(const float4*)(Ap);
        float4 a1 = *(const float4*)(Ap + 4);
        float4 bv = *(const float4*)(Bp);
        float n0 = a0.x * rowI, n1 = a0.y * rowI, n2 = a0.z * rowI, n3 = a0.w * rowI;
        float n4 = a1.x * rowI, n5 = a1.y * rowI, n6 = a1.z * rowI, n7 = a1.w * rowI;
        *(float4*)(Ap)     = make_float4(n0, n1, n2, n3);
        *(float4*)(Ap + 4) = make_float4(n4, n5, n6, n7);
        As[0][ac + 0][ar] = to_tf32(n0); As[0][ac + 1][ar] = to_tf32(n1);
        As[0][ac + 2][ar] = to_tf32(n2); As[0][ac + 3][ar] = to_tf32(n3);
        As[0][ac + 4][ar] = to_tf32(n4); As[0][ac + 5][ar] = to_tf32(n5);
        As[0][ac + 6][ar] = to_tf32(n6); As[0][ac + 7][ar] = to_tf32(n7);
        float4 bt = make_float4(to_tf32(bv.x), to_tf32(bv.y), to_tf32(bv.z), to_tf32(bv.w));
        *(float4*)&Bs[0][br][bc] = bt;
    }
    __syncthreads();

    for (int c = 1; c < SEQ / 16; c++) {
        float* Ac = Ap + c * 16;
        float4 a0 = *(const float4*)(Ac);
        float4 a1 = *(const float4*)(Ac + 4);
        float4 bv = *(const float4*)(Bp + (size_t)(c * 16) * HID);
        int pb = (c - 1) & 1, nb = c & 1;
        #pragma unroll
        for (int ks = 0; ks < 16; ks += 8) {
            uint32_t a[2][4];
            #pragma unroll
            for (int mf = 0; mf < 2; mf++) {
                int m0 = m_base + mf * 16 + gid;
                a[mf][0] = __float_as_uint(As[pb][ks + tig][m0]);
                a[mf][1] = __float_as_uint(As[pb][ks + tig][m0 + 8]);
                a[mf][2] = __float_as_uint(As[pb][ks + tig + 4][m0]);
                a[mf][3] = __float_as_uint(As[pb][ks + tig + 4][m0 + 8]);
            }
            #pragma unroll
            for (int nf = 0; nf < 4; nf++) {
                int n0 = n_base + nf * 8 + gid;
                uint32_t b0 = __float_as_uint(Bs[pb][ks + tig][n0]);
                uint32_t b1 = __float_as_uint(Bs[pb][ks + tig + 4][n0]);
                mma_tf32(acc[0][nf], a[0], b0, b1);
                mma_tf32(acc[1][nf], a[1], b0, b1);
            }
        }
        float n0 = a0.x * rowI, n1 = a0.y * rowI, n2 = a0.z * rowI, n3 = a0.w * rowI;
        float n4 = a1.x * rowI, n5 = a1.y * rowI, n6 = a1.z * rowI, n7 = a1.w * rowI;
        *(float4*)(Ac)     = make_float4(n0, n1, n2, n3);
        *(float4*)(Ac + 4) = make_float4(n4, n5, n6, n7);
        As[nb][ac + 0][ar] = to_tf32(n0); As[nb][ac + 1][ar] = to_tf32(n1);
        As[nb][ac + 2][ar] = to_tf32(n2); As[nb][ac + 3][ar] = to_tf32(n3);
        As[nb][ac + 4][ar] = to_tf32(n4); As[nb][ac + 5][ar] = to_tf32(n5);
        As[nb][ac + 6][ar] = to_tf32(n6); As[nb][ac + 7][ar] = to_tf32(n7);
        float4 bt = make_float4(to_tf32(bv.x), to_tf32(bv.y), to_tf32(bv.z), to_tf32(bv.w));
        *(float4*)&Bs[nb][br][bc] = bt;
        __syncthreads();
    }
    {
        int lb = (SEQ / 16 - 1) & 1;
        #pragma unroll
        for (int ks = 0; ks < 16; ks += 8) {
            uint32_t a[2][4];
            #pragma unroll
            for (int mf = 0; mf < 2; mf++) {
                int m0 = m_base + mf * 16 + gid;
                a[mf][0] = __float_as_uint(As[lb][ks + tig][m0]);
                a[mf][1] = __float_as_uint(As[lb][ks + tig][m0 + 8]);
                a[mf][2] = __float_as_uint(As[lb][ks + tig + 4][m0]);
                a[mf][3] = __float_as_uint(As[lb][ks + tig + 4][m0 + 8]);
            }
            #pragma unroll
            for (int nf = 0; nf < 4; nf++) {
                int n0 = n_base + nf * 8 + gid;
                uint32_t b0 = __float_as_uint(Bs[lb][ks + tig][n0]);
                uint32_t b1 = __float_as_uint(Bs[lb][ks + tig + 4][n0]);
                mma_tf32(acc[0][nf], a[0], b0, b1);
                mma_tf32(acc[1][nf], a[1], b0, b1);
            }
        }
    }

    float* Ob = O + (size_t)b * SEQ * HID + h * HDIM + (size_t)bm * HID;
    #pragma unroll
    for (int mf = 0; mf < 2; mf++) {
        int r0 = m_base + mf * 16 + gid;
        #pragma unroll
        for (int nf = 0; nf < 4; nf++) {
            int col = n_base + nf * 8 + tig * 2;
            *(float2*)(Ob + (size_t)r0 * HID + col)       = make_float2(acc[mf][nf][0], acc[mf][nf][1]);
            *(float2*)(Ob + (size_t)(r0 + 8) * HID + col) = make_float2(acc[mf][nf][2], acc[mf][nf][3]);
        }
    }
}

// ---------------- launch ----------------
extern "C" void kernel_launch(void* const* d_in, const int* in_sizes, int n_in,
                              void* d_out, int out_size) {
    const float* hidden = (const float*)d_in[0];
    const float* ln1g = (const float*)d_in[1];
    const float* ln1b = (const float*)d_in[2];
    const float* Wq = (const float*)d_in[3];
    const float* bq = (const float*)d_in[4];
    const float* Wk = (const float*)d_in[5];
    const float* bk = (const float*)d_in[6];
    const float* Wv = (const float*)d_in[7];
    const float* bv = (const float*)d_in[8];
    const float* Wo = (const float*)d_in[9];
    const float* bo = (const float*)d_in[10];
    const float* lam = (const float*)d_in[11];
    const float* ln2g = (const float*)d_in[12];
    const float* ln2b = (const float*)d_in[13];
    const float* W1 = (const float*)d_in[14];
    const float* b1 = (const float*)d_in[15];
    const float* W2 = (const float*)d_in[16];
    const float* b2 = (const float*)d_in[17];

    float* out0 = (float*)d_out;
    float* attn = out0 + (size_t)MTOT * HID;  // [B,NH,S,S] follows [B,S,H]

    float *x, *q, *k, *v, *ao, *r1, *y, *ff;
    cudaGetSymbolAddress((void**)&x,  g_x);
    cudaGetSymbolAddress((void**)&q,  g_q);
    cudaGetSymbolAddress((void**)&k,  g_k);
    cudaGetSymbolAddress((void**)&v,  g_v);
    cudaGetSymbolAddress((void**)&ao, g_ao);
    cudaGetSymbolAddress((void**)&r1, g_r1);
    cudaGetSymbolAddress((void**)&y,  g_y);
    cudaGetSymbolAddress((void**)&ff, g_ff);

    float* pS = y + PS_OFF;
    float* gI = y + GI_OFF;

    int epiGrid = (MTOT * HID) / (256 * 4);   // 1536

    ln_kernel<<<MTOT, 256>>>(hidden, ln1g, ln1b, x);
    qkv_kernel<<<dim3(18, 16), 256>>>(x, Wq, Wk, Wv, bq, bk, bv, q, k, v);
    dist_kernel<<<dim3(SEQ / 64, SEQ / 128, BHTOT), 256>>>(q, k, lam, attn, pS);
    stats_reduce<<<(BHTOT * SEQ) / 256, 256>>>(pS, gI);
    pv_kernel<<<dim3(SEQ / 128, 1, BHTOT), 256>>>(attn, v, gI, ao);
    // Wo with split-K=2: partials in g_x (x free) and g_ff (free until FF1)
    gemm_split_kernel<<<dim3(6, 16, 2), 256>>>(ao, HID, Wo, HID, x, ff);
    epi_kernel<<<epiGrid, 256>>>(x, ff, bo, hidden, r1);
    ln_kernel<<<MTOT, 256>>>(r1, ln2g, ln2b, y);   // overwrites stats (already consumed)
    gemm_kernel<<<dim3(24, 16), 256>>>(y, HID, W1, FFD, b1, ff, 2);          // gelu (N=3072)
    // FF2 with split-K=2: partials in g_x and g_q (both free now)
    gemm_split_kernel<<<dim3(6, 16, 2), 256>>>(ff, FFD, W2, HID, x, q);
    epi_kernel<<<epiGrid, 256>>>(x, q, b2, r1, out0);
}

// round 13
// speedup vs baseline: 1.0246x; 1.0246x over previous
#include <cuda_runtime.h>
#include <math.h>
#include <stdint.h>

#define SEQ   1024
#define BATCH 2
#define HID   768
#define NHEAD 12
#define HDIM  64
#define FFD   3072
#define MTOT  (BATCH*SEQ)   // 2048
#define BHTOT (BATCH*NHEAD) // 24

#define APAD 136
#define BPAD 72
#define BPAD2 136

// ---------------- scratch (device globals: no allocation allowed) ----------------
__device__ float g_x [MTOT*HID];
__device__ float g_q [MTOT*HID];
__device__ float g_k [MTOT*HID];
__device__ float g_v [MTOT*HID];
__device__ float g_ao[MTOT*HID];
__device__ float g_r1[MTOT*HID];
__device__ float g_y [MTOT*HID];   // hosts softmax partial sums before ln2 reuses it
__device__ float g_ff[MTOT*FFD];

#define PS_OFF   0   // 24576 rows x 16 tile-sums inside g_y

// ---------------- helpers ----------------
__device__ __forceinline__ unsigned long long f2add(unsigned long long a, unsigned long long b) {
    unsigned long long r;
    asm("add.rn.f32x2 %0, %1, %2;" : "=l"(r) : "l"(a), "l"(b));
    return r;
}

__device__ __forceinline__ float gelu1(float v) {
    return 0.5f * v * (1.f + erff(v * 0.70710678118654752f));
}

__device__ __forceinline__ float to_tf32(float x) {
    uint32_t u;
    asm("cvt.rna.tf32.f32 %0, %1;" : "=r"(u) : "f"(x));
    return __uint_as_float(u);
}

__device__ __forceinline__ void mma_tf32(float (&c)[4], const uint32_t (&a)[4],
                                         uint32_t b0, uint32_t b1) {
    asm("mma.sync.aligned.m16n8k8.row.col.f32.tf32.tf32.f32 "
        "{%0,%1,%2,%3}, {%4,%5,%6,%7}, {%8,%9}, {%0,%1,%2,%3};"
        : "+f"(c[0]), "+f"(c[1]), "+f"(c[2]), "+f"(c[3])
        : "r"(a[0]), "r"(a[1]), "r"(a[2]), "r"(a[3]), "r"(b0), "r"(b1));
}

// ---------------- LayerNorm: one block per row of 768 ----------------
__global__ void ln_kernel(const float* __restrict__ in, const float* __restrict__ g,
                          const float* __restrict__ b, float* __restrict__ out) {
    int row = blockIdx.x;
    const float* x = in + (size_t)row * HID;
    int t = threadIdx.x;
    float v0 = x[t], v1 = x[t + 256], v2 = x[t + 512];
    float s  = v0 + v1 + v2;
    float sq = v0 * v0 + v1 * v1 + v2 * v2;
    __shared__ float sh[16];
    #pragma unroll
    for (int o = 16; o; o >>= 1) {
        s  += __shfl_xor_sync(0xffffffffu, s,  o);
        sq += __shfl_xor_sync(0xffffffffu, sq, o);
    }
    int w = t >> 5, l = t & 31;
    if (!l) { sh[w] = s; sh[w + 8] = sq; }
    __syncthreads();
    if (w == 0) {
        float a = (l < 8) ? sh[l] : 0.f;
        float c = (l < 8) ? sh[l + 8] : 0.f;
        #pragma unroll
        for (int o = 4; o; o >>= 1) {
            a += __shfl_xor_sync(0xffffffffu, a, o);
            c += __shfl_xor_sync(0xffffffffu, c, o);
        }
        if (!l) { sh[0] = a; sh[1] = c; }
    }
    __syncthreads();
    float mean = sh[0] * (1.f / HID);
    float var  = sh[1] * (1.f / HID) - mean * mean;
    float rs   = rsqrtf(var + 1e-5f);
    float* o = out + (size_t)row * HID;
    o[t]       = (v0 - mean) * rs * g[t]       + b[t];
    o[t + 256] = (v1 - mean) * rs * g[t + 256] + b[t + 256];
    o[t + 512] = (v2 - mean) * rs * g[t + 512] + b[t + 512];
}

// ======================= tf32 128x128 engine (qkv / Wo / FF) =======================
__device__ __forceinline__ void mma_compute128(
    const float (*Ab)[APAD], const float (*Bb)[BPAD2],
    int m_base, int n_base, int gid, int tig, float (&acc)[4][4][4])
{
    #pragma unroll
    for (int ks = 0; ks < 16; ks += 8) {
        uint32_t a[4][4];
        #pragma unroll
        for (int mf = 0; mf < 4; mf++) {
            int m0 = m_base + mf * 16 + gid;
            a[mf][0] = __float_as_uint(Ab[ks + tig][m0]);
            a[mf][1] = __float_as_uint(Ab[ks + tig][m0 + 8]);
            a[mf][2] = __float_as_uint(Ab[ks + tig + 4][m0]);
            a[mf][3] = __float_as_uint(Ab[ks + tig + 4][m0 + 8]);
        }
        #pragma unroll
        for (int nf = 0; nf < 4; nf++) {
            int n0 = n_base + nf * 8 + gid;
            uint32_t b0 = __float_as_uint(Bb[ks + tig][n0]);
            uint32_t b1 = __float_as_uint(Bb[ks + tig + 4][n0]);
            #pragma unroll
            for (int mf = 0; mf < 4; mf++)
                mma_tf32(acc[mf][nf], a[mf], b0, b1);
        }
    }
}

__device__ __forceinline__ void mma_tile128(
    const float* __restrict__ A, int lda,
    const float* __restrict__ B, int ldb,
    int kLen,
    float (*As)[16][APAD], float (*Bs)[16][BPAD2],
    float (&acc)[4][4][4])
{
    int tid = threadIdx.x;
    int ar = tid >> 1, ac = (tid & 1) * 8;
    int br = tid >> 4, bc = (tid & 15) * 4;
    int lane = tid & 31, wid = tid >> 5;
    int gid = lane >> 2, tig = lane & 3;
    int m_base = (wid & 1) * 64, n_base = (wid >> 1) * 32;

    const float* Ap = A + (size_t)ar * lda + ac;
    const float* Bp = B + (size_t)br * ldb + bc;

    {
        float4 av0 = *(const float4*)(Ap);
        float4 av1 = *(const float4*)(Ap + 4);
        float4 bv0 = *(const float4*)(Bp);
        float4 bv1 = *(const float4*)(Bp + 64);
        As[0][ac + 0][ar] = to_tf32(av0.x); As[0][ac + 1][ar] = to_tf32(av0.y);
        As[0][ac + 2][ar] = to_tf32(av0.z); As[0][ac + 3][ar] = to_tf32(av0.w);
        As[0][ac + 4][ar] = to_tf32(av1.x); As[0][ac + 5][ar] = to_tf32(av1.y);
        As[0][ac + 6][ar] = to_tf32(av1.z); As[0][ac + 7][ar] = to_tf32(av1.w);
        float4 bt0 = make_float4(to_tf32(bv0.x), to_tf32(bv0.y), to_tf32(bv0.z), to_tf32(bv0.w));
        float4 bt1 = make_float4(to_tf32(bv1.x), to_tf32(bv1.y), to_tf32(bv1.z), to_tf32(bv1.w));
        *(float4*)&Bs[0][br][bc]      = bt0;
        *(float4*)&Bs[0][br][bc + 64] = bt1;
    }
    __syncthreads();

    int kc = kLen >> 4;
    for (int c = 1; c < kc; c++) {
        const float* Ac = Ap + c * 16;
        const float* Bc = Bp + (size_t)(c * 16) * ldb;
        float4 av0 = *(const float4*)(Ac);
        float4 av1 = *(const float4*)(Ac + 4);
        float4 bv0 = *(const float4*)(Bc);
        float4 bv1 = *(const float4*)(Bc + 64);
        int pb = (c - 1) & 1, nb = c & 1;
        mma_compute128(As[pb], Bs[pb], m_base, n_base, gid, tig, acc);
        As[nb][ac + 0][ar] = to_tf32(av0.x); As[nb][ac + 1][ar] = to_tf32(av0.y);
        As[nb][ac + 2][ar] = to_tf32(av0.z); As[nb][ac + 3][ar] = to_tf32(av0.w);
        As[nb][ac + 4][ar] = to_tf32(av1.x); As[nb][ac + 5][ar] = to_tf32(av1.y);
        As[nb][ac + 6][ar] = to_tf32(av1.z); As[nb][ac + 7][ar] = to_tf32(av1.w);
        float4 bt0 = make_float4(to_tf32(bv0.x), to_tf32(bv0.y), to_tf32(bv0.z), to_tf32(bv0.w));
        float4 bt1 = make_float4(to_tf32(bv1.x), to_tf32(bv1.y), to_tf32(bv1.z), to_tf32(bv1.w));
        *(float4*)&Bs[nb][br][bc]      = bt0;
        *(float4*)&Bs[nb][br][bc + 64] = bt1;
        __syncthreads();
    }
    int lb = (kc - 1) & 1;
    mma_compute128(As[lb], Bs[lb], m_base, n_base, gid, tig, acc);
}

// ---------------- fused QKV: grid (18,16); blockIdx.x/6 selects matrix ----------------
__global__ void __launch_bounds__(256, 2) qkv_kernel(
    const float* __restrict__ x,
    const float* __restrict__ Wq, const float* __restrict__ Wk, const float* __restrict__ Wv,
    const float* __restrict__ bq, const float* __restrict__ bk, const float* __restrict__ bv,
    float* __restrict__ q, float* __restrict__ k, float* __restrict__ v)
{
    __shared__ float As[2][16][APAD];
    __shared__ float Bs[2][16][BPAD2];
    int sel = blockIdx.x / 6;
    int bn  = (blockIdx.x % 6) * 128;
    int bm  = blockIdx.y * 128;
    const float* B    = sel == 0 ? Wq : (sel == 1 ? Wk : Wv);
    const float* bias = sel == 0 ? bq : (sel == 1 ? bk : bv);
    float* C          = sel == 0 ? q  : (sel == 1 ? k  : v);
    float acc[4][4][4] = {};
    mma_tile128(x + (size_t)bm * HID, HID, B + bn, HID, HID, As, Bs, acc);
    int tid = threadIdx.x, lane = tid & 31, wid = tid >> 5;
    int gid = lane >> 2, tig = lane & 3;
    int m_base = (wid & 1) * 64, n_base = (wid >> 1) * 32;
    #pragma unroll
    for (int mf = 0; mf < 4; mf++) {
        int r0 = bm + m_base + mf * 16 + gid;
        #pragma unroll
        for (int nf = 0; nf < 4; nf++) {
            int col = bn + n_base + nf * 8 + tig * 2;
            float2 bi = *(const float2*)(bias + col);
            *(float2*)(C + (size_t)r0 * HID + col) =
                make_float2(acc[mf][nf][0] + bi.x, acc[mf][nf][1] + bi.y);
            *(float2*)(C + (size_t)(r0 + 8) * HID + col) =
                make_float2(acc[mf][nf][2] + bi.x, acc[mf][nf][3] + bi.y);
        }
    }
}

// ---------------- generic gemm: grid (N/128, M/128); mode 0=+bias 2=gelu(+bias) ----------------
__global__ void __launch_bounds__(256, 2) gemm_kernel(
    const float* __restrict__ A, int K,
    const float* __restrict__ B, int N,
    const float* __restrict__ bias,
    float* __restrict__ C, int mode)
{
    __shared__ float As[2][16][APAD];
    __shared__ float Bs[2][16][BPAD2];
    int bm = blockIdx.y * 128, bn = blockIdx.x * 128;
    float acc[4][4][4] = {};
    mma_tile128(A + (size_t)bm * K, K, B + bn, N, K, As, Bs, acc);
    int tid = threadIdx.x, lane = tid & 31, wid = tid >> 5;
    int gid = lane >> 2, tig = lane & 3;
    int m_base = (wid & 1) * 64, n_base = (wid >> 1) * 32;
    #pragma unroll
    for (int mf = 0; mf < 4; mf++) {
        int r0 = bm + m_base + mf * 16 + gid;
        #pragma unroll
        for (int nf = 0; nf < 4; nf++) {
            int col = bn + n_base + nf * 8 + tig * 2;
            float2 bi = *(const float2*)(bias + col);
            float o0 = acc[mf][nf][0] + bi.x, o1 = acc[mf][nf][1] + bi.y;
            float o2 = acc[mf][nf][2] + bi.x, o3 = acc[mf][nf][3] + bi.y;
            if (mode == 2) { o0 = gelu1(o0); o1 = gelu1(o1); o2 = gelu1(o2); o3 = gelu1(o3); }
            *(float2*)(C + (size_t)r0 * N + col)       = make_float2(o0, o1);
            *(float2*)(C + (size_t)(r0 + 8) * N + col) = make_float2(o2, o3);
        }
    }
}

// ---------------- split-K=2 gemm: grid (N/128, M/128, 2) -> raw partials ----------------
__global__ void __launch_bounds__(256, 2) gemm_split_kernel(
    const float* __restrict__ A, int K,
    const float* __restrict__ B, int N,
    float* __restrict__ P1, float* __restrict__ P2)
{
    __shared__ float As[2][16][APAD];
    __shared__ float Bs[2][16][BPAD2];
    int bm = blockIdx.y * 128, bn = blockIdx.x * 128;
    int half = K >> 1, z = blockIdx.z;
    float acc[4][4][4] = {};
    mma_tile128(A + (size_t)bm * K + z * half, K,
                B + (size_t)(z * half) * N + bn, N, half, As, Bs, acc);
    float* C = z ? P2 : P1;
    int tid = threadIdx.x, lane = tid & 31, wid = tid >> 5;
    int gid = lane >> 2, tig = lane & 3;
    int m_base = (wid & 1) * 64, n_base = (wid >> 1) * 32;
    #pragma unroll
    for (int mf = 0; mf < 4; mf++) {
        int r0 = bm + m_base + mf * 16 + gid;
        #pragma unroll
        for (int nf = 0; nf < 4; nf++) {
            int col = bn + n_base + nf * 8 + tig * 2;
            *(float2*)(C + (size_t)r0 * N + col)       = make_float2(acc[mf][nf][0], acc[mf][nf][1]);
            *(float2*)(C + (size_t)(r0 + 8) * N + col) = make_float2(acc[mf][nf][2], acc[mf][nf][3]);
        }
    }
}

// ---------------- epilogue: out = p1 + p2 + bias + res ----------------
__global__ void epi_kernel(const float* __restrict__ p1, const float* __restrict__ p2,
                           const float* __restrict__ bias, const float* __restrict__ res,
                           float* __restrict__ out)
{
    int idx = (blockIdx.x * 256 + threadIdx.x) * 4;
    int col = idx % HID;
    float4 a  = *(const float4*)(p1 + idx);
    float4 b  = *(const float4*)(p2 + idx);
    float4 r  = *(const float4*)(res + idx);
    float4 bi = *(const float4*)(bias + col);
    float4 o = make_float4(a.x + b.x + r.x + bi.x, a.y + b.y + r.y + bi.y,
                           a.z + b.z + r.z + bi.z, a.w + b.w + r.w + bi.w);
    *(float4*)(out + idx) = o;
}

// ---------------- L1 distance -> exp(score) + per-tile row sums ----------------
// Scores always <= 0, |score| << 87 -> exp without max-subtraction is exact.
__global__ void __launch_bounds__(256) dist_kernel(
    const float* __restrict__ Q, const float* __restrict__ Km,
    const float* __restrict__ lamp, float* __restrict__ attn,
    float* __restrict__ pS)
{
    __shared__ unsigned long long Qs[32][128];   // [d-pair][q-row]
    __shared__ unsigned long long Ks[32][64];    // negated K
    int bh = blockIdx.z, b = bh / NHEAD, h = bh - b * NHEAD;
    int qbase = blockIdx.y * 128, kbase = blockIdx.x * 64;
    const float* Qb = Q  + (size_t)b * SEQ * HID + h * HDIM + (size_t)qbase * HID;
    const float* Kb = Km + (size_t)b * SEQ * HID + h * HDIM + (size_t)kbase * HID;
    int tid = threadIdx.x;

    union F2U { float2 f; unsigned long long u; };
    {
        int row = tid >> 1, hh = (tid & 1) * 32;
        #pragma unroll
        for (int i = 0; i < 8; i++) {
            float4 qv = *(const float4*)(Qb + (size_t)row * HID + hh + i * 4);
            F2U t;
            t.f = make_float2(qv.x, qv.y); Qs[(hh >> 1) + i * 2][row]     = t.u;
            t.f = make_float2(qv.z, qv.w); Qs[(hh >> 1) + i * 2 + 1][row] = t.u;
        }
    }
    {
        int row = tid >> 2, kq = (tid & 3) * 16;
        #pragma unroll
        for (int i = 0; i < 4; i++) {
            float4 kv = *(const float4*)(Kb + (size_t)row * HID + kq + i * 4);
            F2U t;
            t.f = make_float2(-kv.x, -kv.y); Ks[(kq >> 1) + i * 2][row]     = t.u;
            t.f = make_float2(-kv.z, -kv.w); Ks[(kq >> 1) + i * 2 + 1][row] = t.u;
        }
    }
    __syncthreads();

    int tx = tid & 15, ty = tid >> 4;
    int qs = ty * 8, ks = tx * 4;
    unsigned long long acc[8][4] = {};
    const unsigned long long MASK = 0x7FFFFFFF7FFFFFFFull;
    #pragma unroll 8
    for (int d = 0; d < 32; d++) {
        unsigned long long qv[8], kv[4];
        *(ulonglong2*)&qv[0] = *(const ulonglong2*)&Qs[d][qs];
        *(ulonglong2*)&qv[2] = *(const ulonglong2*)&Qs[d][qs + 2];
        *(ulonglong2*)&qv[4] = *(const ulonglong2*)&Qs[d][qs + 4];
        *(ulonglong2*)&qv[6] = *(const ulonglong2*)&Qs[d][qs + 6];
        *(ulonglong2*)&kv[0] = *(const ulonglong2*)&Ks[d][ks];
        *(ulonglong2*)&kv[2] = *(const ulonglong2*)&Ks[d][ks + 2];
        #pragma unroll
        for (int i = 0; i < 8; i++)
            #pragma unroll
            for (int j = 0; j < 4; j++) {
                unsigned long long df = f2add(qv[i], kv[j]) & MASK;
                acc[i][j] = f2add(acc[i][j], df);
            }
    }
    float c = -(*lamp) * 0.125f;   // scale = 1/sqrt(64)
    float* outp = attn + (size_t)bh * SEQ * SEQ + (size_t)(qbase + qs) * SEQ + kbase + ks;
    size_t srow = ((size_t)bh * SEQ + qbase + qs) * 16 + blockIdx.x;
    #pragma unroll
    for (int i = 0; i < 8; i++) {
        F2U t;
        float e0, e1, e2, e3;
        t.u = acc[i][0]; e0 = __expf(c * (t.f.x + t.f.y));
        t.u = acc[i][1]; e1 = __expf(c * (t.f.x + t.f.y));
        t.u = acc[i][2]; e2 = __expf(c * (t.f.x + t.f.y));
        t.u = acc[i][3]; e3 = __expf(c * (t.f.x + t.f.y));
        *(float4*)(outp + (size_t)i * SEQ) = make_float4(e0, e1, e2, e3);
        float s = e0 + e1 + e2 + e3;
        #pragma unroll
        for (int o = 8; o; o >>= 1) s += __shfl_xor_sync(0xffffffffu, s, o);
        if (tx == 0) pS[srow + (size_t)i * 16] = s;
    }
}

// ---------------- fused stats-fold + normalize + attn write + attn@V: grid (8,1,24) ----------------
__global__ void __launch_bounds__(256, 2) pv_kernel(
    float* __restrict__ attn, const float* __restrict__ V,
    const float* __restrict__ pS, float* __restrict__ O)
{
    __shared__ float As[2][16][APAD];
    __shared__ float Bs[2][16][BPAD];
    __shared__ float smI[128];
    int bh = blockIdx.z, b = bh / NHEAD, h = bh - b * NHEAD;
    int bm = blockIdx.x * 128;
    float* A        = attn + (size_t)bh * SEQ * SEQ + (size_t)bm * SEQ;
    const float* Bv = V + (size_t)b * SEQ * HID + h * HDIM;
    int tid = threadIdx.x;
    if (tid < 128) {
        // fold 16 tile-sums for this row (each row owned by exactly one pv block)
        const float* s16 = pS + ((size_t)bh * SEQ + bm + tid) * 16;
        float s = 0.f;
        #pragma unroll
        for (int j = 0; j < 16; j += 4) {
            float4 a4 = *(const float4*)(s16 + j);
            s += a4.x + a4.y + a4.z + a4.w;
        }
        smI[tid] = 1.f / s;
    }
    __syncthreads();

    int ar = tid >> 1, ac = (tid & 1) * 8;
    int br = tid >> 4, bc = (tid & 15) * 4;
    int lane = tid & 31, wid = tid >> 5;
    int gid = lane >> 2, tig = lane & 3;
    int m_base = (wid & 3) * 32, n_base = (wid >> 2) * 32;
    float rowI = smI[ar];
    float acc[2][4][4] = {};

    float* Ap       = A + (size_t)ar * SEQ + ac;
    const float* Bp = Bv + (size_t)br * HID + bc;

    {   // chunk 0: load exp, normalize (FMUL), write back, stage tf32
        float4 a0 = *(const float4*)(Ap);
        float4 a1 = *(const float4*)(Ap + 4);
        float4 bv = *(const float4*)(Bp);
        float n0 = a0.x * rowI, n1 = a0.y * rowI, n2 = a0.z * rowI, n3 = a0.w * rowI;
        float n4 = a1.x * rowI, n5 = a1.y * rowI, n6 = a1.z * rowI, n7 = a1.w * rowI;
        *(float4*)(Ap)     = make_float4(n0, n1, n2, n3);
        *(float4*)(Ap + 4) = make_float4(n4, n5, n6, n7);
        As[0][ac + 0][ar] = to_tf32(n0); As[0][ac + 1][ar] = to_tf32(n1);
        As[0][ac + 2][ar] = to_tf32(n2); As[0][ac + 3][ar] = to_tf32(n3);
        As[0][ac + 4][ar] = to_tf32(n4); As[0][ac + 5][ar] = to_tf32(n5);
        As[0][ac + 6][ar] = to_tf32(n6); As[0][ac + 7][ar] = to_tf32(n7);
        float4 bt = make_float4(to_tf32(bv.x), to_tf32(bv.y), to_tf32(bv.z), to_tf32(bv.w));
        *(float4*)&Bs[0][br][bc] = bt;
    }
    __syncthreads();

    for (int c = 1; c < SEQ / 16; c++) {
        float* Ac = Ap + c * 16;
        float4 a0 = *(const float4*)(Ac);
        float4 a1 = *(const float4*)(Ac + 4);
        float4 bv = *(const float4*)(Bp + (size_t)(c * 16) * HID);
        int pb = (c - 1) & 1, nb = c & 1;
        #pragma unroll
        for (int ks = 0; ks < 16; ks += 8) {
            uint32_t a[2][4];
            #pragma unroll
            for (int mf = 0; mf < 2; mf++) {
                int m0 = m_base + mf * 16 + gid;
                a[mf][0] = __float_as_uint(As[pb][ks + tig][m0]);
                a[mf][1] = __float_as_uint(As[pb][ks + tig][m0 + 8]);
                a[mf][2] = __float_as_uint(As[pb][ks + tig + 4][m0]);
                a[mf][3] = __float_as_uint(As[pb][ks + tig + 4][m0 + 8]);
            }
            #pragma unroll
            for (int nf = 0; nf < 4; nf++) {
                int n0 = n_base + nf * 8 + gid;
                uint32_t b0 = __float_as_uint(Bs[pb][ks + tig][n0]);
                uint32_t b1 = __float_as_uint(Bs[pb][ks + tig + 4][n0]);
                mma_tf32(acc[0][nf], a[0], b0, b1);
                mma_tf32(acc[1][nf], a[1], b0, b1);
            }
        }
        float n0 = a0.x * rowI, n1 = a0.y * rowI, n2 = a0.z * rowI, n3 = a0.w * rowI;
        float n4 = a1.x * rowI, n5 = a1.y * rowI, n6 = a1.z * rowI, n7 = a1.w * rowI;
        *(float4*)(Ac)     = make_float4(n0, n1, n2, n3);
        *(float4*)(Ac + 4) = make_float4(n4, n5, n6, n7);
        As[nb][ac + 0][ar] = to_tf32(n0); As[nb][ac + 1][ar] = to_tf32(n1);
        As[nb][ac + 2][ar] = to_tf32(n2); As[nb][ac + 3][ar] = to_tf32(n3);
        As[nb][ac + 4][ar] = to_tf32(n4); As[nb][ac + 5][ar] = to_tf32(n5);
        As[nb][ac + 6][ar] = to_tf32(n6); As[nb][ac + 7][ar] = to_tf32(n7);
        float4 bt = make_float4(to_tf32(bv.x), to_tf32(bv.y), to_tf32(bv.z), to_tf32(bv.w));
        *(float4*)&Bs[nb][br][bc] = bt;
        __syncthreads();
    }
    {
        int lb = (SEQ / 16 - 1) & 1;
        #pragma unroll
        for (int ks = 0; ks < 16; ks += 8) {
            uint32_t a[2][4];
            #pragma unroll
            for (int mf = 0; mf < 2; mf++) {
                int m0 = m_base + mf * 16 + gid;
                a[mf][0] = __float_as_uint(As[lb][ks + tig][m0]);
                a[mf][1] = __float_as_uint(As[lb][ks + tig][m0 + 8]);
                a[mf][2] = __float_as_uint(As[lb][ks + tig + 4][m0]);
                a[mf][3] = __float_as_uint(As[lb][ks + tig + 4][m0 + 8]);
            }
            #pragma unroll
            for (int nf = 0; nf < 4; nf++) {
                int n0 = n_base + nf * 8 + gid;
                uint32_t b0 = __float_as_uint(Bs[lb][ks + tig][n0]);
                uint32_t b1 = __float_as_uint(Bs[lb][ks + tig + 4][n0]);
                mma_tf32(acc[0][nf], a[0], b0, b1);
                mma_tf32(acc[1][nf], a[1], b0, b1);
            }
        }
    }

    float* Ob = O + (size_t)b * SEQ * HID + h * HDIM + (size_t)bm * HID;
    #pragma unroll
    for (int mf = 0; mf < 2; mf++) {
        int r0 = m_base + mf * 16 + gid;
        #pragma unroll
        for (int nf = 0; nf < 4; nf++) {
            int col = n_base + nf * 8 + tig * 2;
            *(float2*)(Ob + (size_t)r0 * HID + col)       = make_float2(acc[mf][nf][0], acc[mf][nf][1]);
            *(float2*)(Ob + (size_t)(r0 + 8) * HID + col) = make_float2(acc[mf][nf][2], acc[mf][nf][3]);
        }
    }
}

// ---------------- launch ----------------
extern "C" void kernel_launch(void* const* d_in, const int* in_sizes, int n_in,
                              void* d_out, int out_size) {
    const float* hidden = (const float*)d_in[0];
    const float* ln1g = (const float*)d_in[1];
    const float* ln1b = (const float*)d_in[2];
    const float* Wq = (const float*)d_in[3];
    const float* bq = (const float*)d_in[4];
    const float* Wk = (const float*)d_in[5];
    const float* bk = (const float*)d_in[6];
    const float* Wv = (const float*)d_in[7];
    const float* bv = (const float*)d_in[8];
    const float* Wo = (const float*)d_in[9];
    const float* bo = (const float*)d_in[10];
    const float* lam = (const float*)d_in[11];
    const float* ln2g = (const float*)d_in[12];
    const float* ln2b = (const float*)d_in[13];
    const float* W1 = (const float*)d_in[14];
    const float* b1 = (const float*)d_in[15];
    const float* W2 = (const float*)d_in[16];
    const float* b2 = (const float*)d_in[17];

    float* out0 = (float*)d_out;
    float* attn = out0 + (size_t)MTOT * HID;  // [B,NH,S,S] follows [B,S,H]

    float *x, *q, *k, *v, *ao, *r1, *y, *ff;
    cudaGetSymbolAddress((void**)&x,  g_x);
    cudaGetSymbolAddress((void**)&q,  g_q);
    cudaGetSymbolAddress((void**)&k,  g_k);
    cudaGetSymbolAddress((void**)&v,  g_v);
    cudaGetSymbolAddress((void**)&ao, g_ao);
    cudaGetSymbolAddress((void**)&r1, g_r1);
    cudaGetSymbolAddress((void**)&y,  g_y);
    cudaGetSymbolAddress((void**)&ff, g_ff);

    float* pS = y + PS_OFF;

    int epiGrid = (MTOT * HID) / (256 * 4);   // 1536

    ln_kernel<<<MTOT, 256>>>(hidden, ln1g, ln1b, x);
    qkv_kernel<<<dim3(18, 16), 256>>>(x, Wq, Wk, Wv, bq, bk, bv, q, k, v);
    dist_kernel<<<dim3(SEQ / 64, SEQ / 128, BHTOT), 256>>>(q, k, lam, attn, pS);
    pv_kernel<<<dim3(SEQ / 128, 1, BHTOT), 256>>>(attn, v, pS, ao);
    // Wo with split-K=2: partials in g_x (x free) and g_ff (free until FF1)
    gemm_split_kernel<<<dim3(6, 16, 2), 256>>>(ao, HID, Wo, HID, x, ff);
    epi_kernel<<<epiGrid, 256>>>(x, ff, bo, hidden, r1);
    ln_kernel<<<MTOT, 256>>>(r1, ln2g, ln2b, y);   // overwrites pS (already consumed)
    gemm_kernel<<<dim3(24, 16), 256>>>(y, HID, W1, FFD, b1, ff, 2);          // gelu (N=3072)
    // FF2 with split-K=2: partials in g_x and g_q (both free now)
    gemm_split_kernel<<<dim3(6, 16, 2), 256>>>(ff, FFD, W2, HID, x, q);
    epi_kernel<<<epiGrid, 256>>>(x, q, b2, r1, out0);
}

// round 14
// speedup vs baseline: 1.0581x; 1.0327x over previous
#include <cuda_runtime.h>
#include <math.h>
#include <stdint.h>

#define SEQ   1024
#define BATCH 2
#define HID   768
#define NHEAD 12
#define HDIM  64
#define FFD   3072
#define MTOT  (BATCH*SEQ)   // 2048
#define BHTOT (BATCH*NHEAD) // 24

#define APAD 136
#define BPAD 72
#define BPAD2 136

// ---------------- scratch (device globals: no allocation allowed) ----------------
__device__ float g_x [MTOT*HID];
__device__ float g_q [MTOT*HID];
__device__ float g_k [MTOT*HID];
__device__ float g_v [MTOT*HID];
__device__ float g_ao[MTOT*HID];
__device__ float g_r1[MTOT*HID];
__device__ float g_y [MTOT*HID];   // hosts softmax partial sums before ln2 reuses it
__device__ float g_ff[MTOT*FFD];

#define PS_OFF   0   // 24576 rows x 16 tile-sums inside g_y

// ---------------- helpers ----------------
__device__ __forceinline__ unsigned long long f2add(unsigned long long a, unsigned long long b) {
    unsigned long long r;
    asm("add.rn.f32x2 %0, %1, %2;" : "=l"(r) : "l"(a), "l"(b));
    return r;
}

__device__ __forceinline__ float gelu1(float v) {
    return 0.5f * v * (1.f + erff(v * 0.70710678118654752f));
}

__device__ __forceinline__ float to_tf32(float x) {
    uint32_t u;
    asm("cvt.rna.tf32.f32 %0, %1;" : "=r"(u) : "f"(x));
    return __uint_as_float(u);
}

__device__ __forceinline__ void mma_tf32(float (&c)[4], const uint32_t (&a)[4],
                                         uint32_t b0, uint32_t b1) {
    asm("mma.sync.aligned.m16n8k8.row.col.f32.tf32.tf32.f32 "
        "{%0,%1,%2,%3}, {%4,%5,%6,%7}, {%8,%9}, {%0,%1,%2,%3};"
        : "+f"(c[0]), "+f"(c[1]), "+f"(c[2]), "+f"(c[3])
        : "r"(a[0]), "r"(a[1]), "r"(a[2]), "r"(a[3]), "r"(b0), "r"(b1));
}

// ---------------- LayerNorm: one block per row of 768 ----------------
__global__ void ln_kernel(const float* __restrict__ in, const float* __restrict__ g,
                          const float* __restrict__ b, float* __restrict__ out) {
    int row = blockIdx.x;
    const float* x = in + (size_t)row * HID;
    int t = threadIdx.x;
    float v0 = x[t], v1 = x[t + 256], v2 = x[t + 512];
    float s  = v0 + v1 + v2;
    float sq = v0 * v0 + v1 * v1 + v2 * v2;
    __shared__ float sh[16];
    #pragma unroll
    for (int o = 16; o; o >>= 1) {
        s  += __shfl_xor_sync(0xffffffffu, s,  o);
        sq += __shfl_xor_sync(0xffffffffu, sq, o);
    }
    int w = t >> 5, l = t & 31;
    if (!l) { sh[w] = s; sh[w + 8] = sq; }
    __syncthreads();
    if (w == 0) {
        float a = (l < 8) ? sh[l] : 0.f;
        float c = (l < 8) ? sh[l + 8] : 0.f;
        #pragma unroll
        for (int o = 4; o; o >>= 1) {
            a += __shfl_xor_sync(0xffffffffu, a, o);
            c += __shfl_xor_sync(0xffffffffu, c, o);
        }
        if (!l) { sh[0] = a; sh[1] = c; }
    }
    __syncthreads();
    float mean = sh[0] * (1.f / HID);
    float var  = sh[1] * (1.f / HID) - mean * mean;
    float rs   = rsqrtf(var + 1e-5f);
    float* o = out + (size_t)row * HID;
    o[t]       = (v0 - mean) * rs * g[t]       + b[t];
    o[t + 256] = (v1 - mean) * rs * g[t + 256] + b[t + 256];
    o[t + 512] = (v2 - mean) * rs * g[t + 512] + b[t + 512];
}

// ======================= tf32 128x128 engine (qkv / Wo / FF) =======================
__device__ __forceinline__ void mma_compute128(
    const float (*Ab)[APAD], const float (*Bb)[BPAD2],
    int m_base, int n_base, int gid, int tig, float (&acc)[4][4][4])
{
    #pragma unroll
    for (int ks = 0; ks < 16; ks += 8) {
        uint32_t a[4][4];
        #pragma unroll
        for (int mf = 0; mf < 4; mf++) {
            int m0 = m_base + mf * 16 + gid;
            a[mf][0] = __float_as_uint(Ab[ks + tig][m0]);
            a[mf][1] = __float_as_uint(Ab[ks + tig][m0 + 8]);
            a[mf][2] = __float_as_uint(Ab[ks + tig + 4][m0]);
            a[mf][3] = __float_as_uint(Ab[ks + tig + 4][m0 + 8]);
        }
        #pragma unroll
        for (int nf = 0; nf < 4; nf++) {
            int n0 = n_base + nf * 8 + gid;
            uint32_t b0 = __float_as_uint(Bb[ks + tig][n0]);
            uint32_t b1 = __float_as_uint(Bb[ks + tig + 4][n0]);
            #pragma unroll
            for (int mf = 0; mf < 4; mf++)
                mma_tf32(acc[mf][nf], a[mf], b0, b1);
        }
    }
}

__device__ __forceinline__ void mma_tile128(
    const float* __restrict__ A, int lda,
    const float* __restrict__ B, int ldb,
    int kLen,
    float (*As)[16][APAD], float (*Bs)[16][BPAD2],
    float (&acc)[4][4][4])
{
    int tid = threadIdx.x;
    int ar = tid >> 1, ac = (tid & 1) * 8;
    int br = tid >> 4, bc = (tid & 15) * 4;
    int lane = tid & 31, wid = tid >> 5;
    int gid = lane >> 2, tig = lane & 3;
    int m_base = (wid & 1) * 64, n_base = (wid >> 1) * 32;

    const float* Ap = A + (size_t)ar * lda + ac;
    const float* Bp = B + (size_t)br * ldb + bc;

    {
        float4 av0 = *(const float4*)(Ap);
        float4 av1 = *(const float4*)(Ap + 4);
        float4 bv0 = *(const float4*)(Bp);
        float4 bv1 = *(const float4*)(Bp + 64);
        As[0][ac + 0][ar] = to_tf32(av0.x); As[0][ac + 1][ar] = to_tf32(av0.y);
        As[0][ac + 2][ar] = to_tf32(av0.z); As[0][ac + 3][ar] = to_tf32(av0.w);
        As[0][ac + 4][ar] = to_tf32(av1.x); As[0][ac + 5][ar] = to_tf32(av1.y);
        As[0][ac + 6][ar] = to_tf32(av1.z); As[0][ac + 7][ar] = to_tf32(av1.w);
        float4 bt0 = make_float4(to_tf32(bv0.x), to_tf32(bv0.y), to_tf32(bv0.z), to_tf32(bv0.w));
        float4 bt1 = make_float4(to_tf32(bv1.x), to_tf32(bv1.y), to_tf32(bv1.z), to_tf32(bv1.w));
        *(float4*)&Bs[0][br][bc]      = bt0;
        *(float4*)&Bs[0][br][bc + 64] = bt1;
    }
    __syncthreads();

    int kc = kLen >> 4;
    for (int c = 1; c < kc; c++) {
        const float* Ac = Ap + c * 16;
        const float* Bc = Bp + (size_t)(c * 16) * ldb;
        float4 av0 = *(const float4*)(Ac);
        float4 av1 = *(const float4*)(Ac + 4);
        float4 bv0 = *(const float4*)(Bc);
        float4 bv1 = *(const float4*)(Bc + 64);
        int pb = (c - 1) & 1, nb = c & 1;
        mma_compute128(As[pb], Bs[pb], m_base, n_base, gid, tig, acc);
        As[nb][ac + 0][ar] = to_tf32(av0.x); As[nb][ac + 1][ar] = to_tf32(av0.y);
        As[nb][ac + 2][ar] = to_tf32(av0.z); As[nb][ac + 3][ar] = to_tf32(av0.w);
        As[nb][ac + 4][ar] = to_tf32(av1.x); As[nb][ac + 5][ar] = to_tf32(av1.y);
        As[nb][ac + 6][ar] = to_tf32(av1.z); As[nb][ac + 7][ar] = to_tf32(av1.w);
        float4 bt0 = make_float4(to_tf32(bv0.x), to_tf32(bv0.y), to_tf32(bv0.z), to_tf32(bv0.w));
        float4 bt1 = make_float4(to_tf32(bv1.x), to_tf32(bv1.y), to_tf32(bv1.z), to_tf32(bv1.w));
        *(float4*)&Bs[nb][br][bc]      = bt0;
        *(float4*)&Bs[nb][br][bc + 64] = bt1;
        __syncthreads();
    }
    int lb = (kc - 1) & 1;
    mma_compute128(As[lb], Bs[lb], m_base, n_base, gid, tig, acc);
}

// ---------------- fused QKV: grid (18,16); blockIdx.x/6 selects matrix ----------------
__global__ void __launch_bounds__(256, 2) qkv_kernel(
    const float* __restrict__ x,
    const float* __restrict__ Wq, const float* __restrict__ Wk, const float* __restrict__ Wv,
    const float* __restrict__ bq, const float* __restrict__ bk, const float* __restrict__ bv,
    float* __restrict__ q, float* __restrict__ k, float* __restrict__ v)
{
    __shared__ float As[2][16][APAD];
    __shared__ float Bs[2][16][BPAD2];
    int sel = blockIdx.x / 6;
    int bn  = (blockIdx.x % 6) * 128;
    int bm  = blockIdx.y * 128;
    const float* B    = sel == 0 ? Wq : (sel == 1 ? Wk : Wv);
    const float* bias = sel == 0 ? bq : (sel == 1 ? bk : bv);
    float* C          = sel == 0 ? q  : (sel == 1 ? k  : v);
    float acc[4][4][4] = {};
    mma_tile128(x + (size_t)bm * HID, HID, B + bn, HID, HID, As, Bs, acc);
    int tid = threadIdx.x, lane = tid & 31, wid = tid >> 5;
    int gid = lane >> 2, tig = lane & 3;
    int m_base = (wid & 1) * 64, n_base = (wid >> 1) * 32;
    #pragma unroll
    for (int mf = 0; mf < 4; mf++) {
        int r0 = bm + m_base + mf * 16 + gid;
        #pragma unroll
        for (int nf = 0; nf < 4; nf++) {
            int col = bn + n_base + nf * 8 + tig * 2;
            float2 bi = *(const float2*)(bias + col);
            *(float2*)(C + (size_t)r0 * HID + col) =
                make_float2(acc[mf][nf][0] + bi.x, acc[mf][nf][1] + bi.y);
            *(float2*)(C + (size_t)(r0 + 8) * HID + col) =
                make_float2(acc[mf][nf][2] + bi.x, acc[mf][nf][3] + bi.y);
        }
    }
}

// ---------------- generic gemm: grid (N/128, M/128); mode 0=+bias 2=gelu(+bias) ----------------
__global__ void __launch_bounds__(256, 2) gemm_kernel(
    const float* __restrict__ A, int K,
    const float* __restrict__ B, int N,
    const float* __restrict__ bias,
    float* __restrict__ C, int mode)
{
    __shared__ float As[2][16][APAD];
    __shared__ float Bs[2][16][BPAD2];
    int bm = blockIdx.y * 128, bn = blockIdx.x * 128;
    float acc[4][4][4] = {};
    mma_tile128(A + (size_t)bm * K, K, B + bn, N, K, As, Bs, acc);
    int tid = threadIdx.x, lane = tid & 31, wid = tid >> 5;
    int gid = lane >> 2, tig = lane & 3;
    int m_base = (wid & 1) * 64, n_base = (wid >> 1) * 32;
    #pragma unroll
    for (int mf = 0; mf < 4; mf++) {
        int r0 = bm + m_base + mf * 16 + gid;
        #pragma unroll
        for (int nf = 0; nf < 4; nf++) {
            int col = bn + n_base + nf * 8 + tig * 2;
            float2 bi = *(const float2*)(bias + col);
            float o0 = acc[mf][nf][0] + bi.x, o1 = acc[mf][nf][1] + bi.y;
            float o2 = acc[mf][nf][2] + bi.x, o3 = acc[mf][nf][3] + bi.y;
            if (mode == 2) { o0 = gelu1(o0); o1 = gelu1(o1); o2 = gelu1(o2); o3 = gelu1(o3); }
            *(float2*)(C + (size_t)r0 * N + col)       = make_float2(o0, o1);
            *(float2*)(C + (size_t)(r0 + 8) * N + col) = make_float2(o2, o3);
        }
    }
}

// ---------------- split-K=2 gemm: grid (N/128, M/128, 2) -> raw partials ----------------
__global__ void __launch_bounds__(256, 2) gemm_split_kernel(
    const float* __restrict__ A, int K,
    const float* __restrict__ B, int N,
    float* __restrict__ P1, float* __restrict__ P2)
{
    __shared__ float As[2][16][APAD];
    __shared__ float Bs[2][16][BPAD2];
    int bm = blockIdx.y * 128, bn = blockIdx.x * 128;
    int half = K >> 1, z = blockIdx.z;
    float acc[4][4][4] = {};
    mma_tile128(A + (size_t)bm * K + z * half, K,
                B + (size_t)(z * half) * N + bn, N, half, As, Bs, acc);
    float* C = z ? P2 : P1;
    int tid = threadIdx.x, lane = tid & 31, wid = tid >> 5;
    int gid = lane >> 2, tig = lane & 3;
    int m_base = (wid & 1) * 64, n_base = (wid >> 1) * 32;
    #pragma unroll
    for (int mf = 0; mf < 4; mf++) {
        int r0 = bm + m_base + mf * 16 + gid;
        #pragma unroll
        for (int nf = 0; nf < 4; nf++) {
            int col = bn + n_base + nf * 8 + tig * 2;
            *(float2*)(C + (size_t)r0 * N + col)       = make_float2(acc[mf][nf][0], acc[mf][nf][1]);
            *(float2*)(C + (size_t)(r0 + 8) * N + col) = make_float2(acc[mf][nf][2], acc[mf][nf][3]);
        }
    }
}

// ---------------- epilogue: out = p1 + p2 + bias + res ----------------
__global__ void epi_kernel(const float* __restrict__ p1, const float* __restrict__ p2,
                           const float* __restrict__ bias, const float* __restrict__ res,
                           float* __restrict__ out)
{
    int idx = (blockIdx.x * 256 + threadIdx.x) * 4;
    int col = idx % HID;
    float4 a  = *(const float4*)(p1 + idx);
    float4 b  = *(const float4*)(p2 + idx);
    float4 r  = *(const float4*)(res + idx);
    float4 bi = *(const float4*)(bias + col);
    float4 o = make_float4(a.x + b.x + r.x + bi.x, a.y + b.y + r.y + bi.y,
                           a.z + b.z + r.z + bi.z, a.w + b.w + r.w + bi.w);
    *(float4*)(out + idx) = o;
}

// ---------------- L1 distance -> exp(score) + per-tile row sums ----------------
// Scores always <= 0, |score| << 87 -> exp without max-subtraction is exact.
__global__ void __launch_bounds__(256, 2) dist_kernel(
    const float* __restrict__ Q, const float* __restrict__ Km,
    const float* __restrict__ lamp, float* __restrict__ attn,
    float* __restrict__ pS)
{
    __shared__ unsigned long long Qs[32][128];   // [d-pair][q-row]
    __shared__ unsigned long long Ks[32][64];    // negated K
    int bh = blockIdx.z, b = bh / NHEAD, h = bh - b * NHEAD;
    int qbase = blockIdx.y * 128, kbase = blockIdx.x * 64;
    const float* Qb = Q  + (size_t)b * SEQ * HID + h * HDIM + (size_t)qbase * HID;
    const float* Kb = Km + (size_t)b * SEQ * HID + h * HDIM + (size_t)kbase * HID;
    int tid = threadIdx.x;

    union F2U { float2 f; unsigned long long u; };
    {
        int row = tid >> 1, hh = (tid & 1) * 32;
        #pragma unroll
        for (int i = 0; i < 8; i++) {
            float4 qv = *(const float4*)(Qb + (size_t)row * HID + hh + i * 4);
            F2U t;
            t.f = make_float2(qv.x, qv.y); Qs[(hh >> 1) + i * 2][row]     = t.u;
            t.f = make_float2(qv.z, qv.w); Qs[(hh >> 1) + i * 2 + 1][row] = t.u;
        }
    }
    {
        int row = tid >> 2, kq = (tid & 3) * 16;
        #pragma unroll
        for (int i = 0; i < 4; i++) {
            float4 kv = *(const float4*)(Kb + (size_t)row * HID + kq + i * 4);
            F2U t;
            t.f = make_float2(-kv.x, -kv.y); Ks[(kq >> 1) + i * 2][row]     = t.u;
            t.f = make_float2(-kv.z, -kv.w); Ks[(kq >> 1) + i * 2 + 1][row] = t.u;
        }
    }
    __syncthreads();

    int tx = tid & 15, ty = tid >> 4;
    int qs = ty * 8, ks = tx * 4;
    unsigned long long acc[8][4] = {};
    const unsigned long long MASK = 0x7FFFFFFF7FFFFFFFull;
    #pragma unroll 8
    for (int d = 0; d < 32; d++) {
        unsigned long long qv[8], kv[4];
        *(ulonglong2*)&qv[0] = *(const ulonglong2*)&Qs[d][qs];
        *(ulonglong2*)&qv[2] = *(const ulonglong2*)&Qs[d][qs + 2];
        *(ulonglong2*)&qv[4] = *(const ulonglong2*)&Qs[d][qs + 4];
        *(ulonglong2*)&qv[6] = *(const ulonglong2*)&Qs[d][qs + 6];
        *(ulonglong2*)&kv[0] = *(const ulonglong2*)&Ks[d][ks];
        *(ulonglong2*)&kv[2] = *(const ulonglong2*)&Ks[d][ks + 2];
        #pragma unroll
        for (int i = 0; i < 8; i++)
            #pragma unroll
            for (int j = 0; j < 4; j++) {
                unsigned long long df = f2add(qv[i], kv[j]) & MASK;
                acc[i][j] = f2add(acc[i][j], df);
            }
    }
    float c = -(*lamp) * 0.125f;   // scale = 1/sqrt(64)
    float* outp = attn + (size_t)bh * SEQ * SEQ + (size_t)(qbase + qs) * SEQ + kbase + ks;
    size_t srow = ((size_t)bh * SEQ + qbase + qs) * 16 + blockIdx.x;
    #pragma unroll
    for (int i = 0; i < 8; i++) {
        F2U t;
        float e0, e1, e2, e3;
        t.u = acc[i][0]; e0 = __expf(c * (t.f.x + t.f.y));
        t.u = acc[i][1]; e1 = __expf(c * (t.f.x + t.f.y));
        t.u = acc[i][2]; e2 = __expf(c * (t.f.x + t.f.y));
        t.u = acc[i][3]; e3 = __expf(c * (t.f.x + t.f.y));
        *(float4*)(outp + (size_t)i * SEQ) = make_float4(e0, e1, e2, e3);
        float s = e0 + e1 + e2 + e3;
        #pragma unroll
        for (int o = 8; o; o >>= 1) s += __shfl_xor_sync(0xffffffffu, s, o);
        if (tx == 0) pS[srow + (size_t)i * 16] = s;
    }
}

// ---------------- fused stats-fold + normalize + attn write + attn@V: grid (8,1,24) ----------------
__global__ void __launch_bounds__(256, 3) pv_kernel(
    float* __restrict__ attn, const float* __restrict__ V,
    const float* __restrict__ pS, float* __restrict__ O)
{
    __shared__ float As[2][16][APAD];
    __shared__ float Bs[2][16][BPAD];
    __shared__ float smI[128];
    int bh = blockIdx.z, b = bh / NHEAD, h = bh - b * NHEAD;
    int bm = blockIdx.x * 128;
    float* A        = attn + (size_t)bh * SEQ * SEQ + (size_t)bm * SEQ;
    const float* Bv = V + (size_t)b * SEQ * HID + h * HDIM;
    int tid = threadIdx.x;
    if (tid < 128) {
        // fold 16 tile-sums for this row (each row owned by exactly one pv block)
        const float* s16 = pS + ((size_t)bh * SEQ + bm + tid) * 16;
        float s = 0.f;
        #pragma unroll
        for (int j = 0; j < 16; j += 4) {
            float4 a4 = *(const float4*)(s16 + j);
            s += a4.x + a4.y + a4.z + a4.w;
        }
        smI[tid] = 1.f / s;
    }
    __syncthreads();

    int ar = tid >> 1, ac = (tid & 1) * 8;
    int br = tid >> 4, bc = (tid & 15) * 4;
    int lane = tid & 31, wid = tid >> 5;
    int gid = lane >> 2, tig = lane & 3;
    int m_base = (wid & 3) * 32, n_base = (wid >> 2) * 32;
    float rowI = smI[ar];
    float acc[2][4][4] = {};

    float* Ap       = A + (size_t)ar * SEQ + ac;
    const float* Bp = Bv + (size_t)br * HID + bc;

    {   // chunk 0: load exp, normalize (FMUL), write back, stage tf32
        float4 a0 = *(const float4*)(Ap);
        float4 a1 = *(const float4*)(Ap + 4);
        float4 bv = *(const float4*)(Bp);
        float n0 = a0.x * rowI, n1 = a0.y * rowI, n2 = a0.z * rowI, n3 = a0.w * rowI;
        float n4 = a1.x * rowI, n5 = a1.y * rowI, n6 = a1.z * rowI, n7 = a1.w * rowI;
        *(float4*)(Ap)     = make_float4(n0, n1, n2, n3);
        *(float4*)(Ap + 4) = make_float4(n4, n5, n6, n7);
        As[0][ac + 0][ar] = to_tf32(n0); As[0][ac + 1][ar] = to_tf32(n1);
        As[0][ac + 2][ar] = to_tf32(n2); As[0][ac + 3][ar] = to_tf32(n3);
        As[0][ac + 4][ar] = to_tf32(n4); As[0][ac + 5][ar] = to_tf32(n5);
        As[0][ac + 6][ar] = to_tf32(n6); As[0][ac + 7][ar] = to_tf32(n7);
        float4 bt = make_float4(to_tf32(bv.x), to_tf32(bv.y), to_tf32(bv.z), to_tf32(bv.w));
        *(float4*)&Bs[0][br][bc] = bt;
    }
    __syncthreads();

    for (int c = 1; c < SEQ / 16; c++) {
        float* Ac = Ap + c * 16;
        float4 a0 = *(const float4*)(Ac);
        float4 a1 = *(const float4*)(Ac + 4);
        float4 bv = *(const float4*)(Bp + (size_t)(c * 16) * HID);
        int pb = (c - 1) & 1, nb = c & 1;
        #pragma unroll
        for (int ks = 0; ks < 16; ks += 8) {
            uint32_t a[2][4];
            #pragma unroll
            for (int mf = 0; mf < 2; mf++) {
                int m0 = m_base + mf * 16 + gid;
                a[mf][0] = __float_as_uint(As[pb][ks + tig][m0]);
                a[mf][1] = __float_as_uint(As[pb][ks + tig][m0 + 8]);
                a[mf][2] = __float_as_uint(As[pb][ks + tig + 4][m0]);
                a[mf][3] = __float_as_uint(As[pb][ks + tig + 4][m0 + 8]);
            }
            #pragma unroll
            for (int nf = 0; nf < 4; nf++) {
                int n0 = n_base + nf * 8 + gid;
                uint32_t b0 = __float_as_uint(Bs[pb][ks + tig][n0]);
                uint32_t b1 = __float_as_uint(Bs[pb][ks + tig + 4][n0]);
                mma_tf32(acc[0][nf], a[0], b0, b1);
                mma_tf32(acc[1][nf], a[1], b0, b1);
            }
        }
        float n0 = a0.x * rowI, n1 = a0.y * rowI, n2 = a0.z * rowI, n3 = a0.w * rowI;
        float n4 = a1.x * rowI, n5 = a1.y * rowI, n6 = a1.z * rowI, n7 = a1.w * rowI;
        *(float4*)(Ac)     = make_float4(n0, n1, n2, n3);
        *(float4*)(Ac + 4) = make_float4(n4, n5, n6, n7);
        As[nb][ac + 0][ar] = to_tf32(n0); As[nb][ac + 1][ar] = to_tf32(n1);
        As[nb][ac + 2][ar] = to_tf32(n2); As[nb][ac + 3][ar] = to_tf32(n3);
        As[nb][ac + 4][ar] = to_tf32(n4); As[nb][ac + 5][ar] = to_tf32(n5);
        As[nb][ac + 6][ar] = to_tf32(n6); As[nb][ac + 7][ar] = to_tf32(n7);
        float4 bt = make_float4(to_tf32(bv.x), to_tf32(bv.y), to_tf32(bv.z), to_tf32(bv.w));
        *(float4*)&Bs[nb][br][bc] = bt;
        __syncthreads();
    }
    {
        int lb = (SEQ / 16 - 1) & 1;
        #pragma unroll
        for (int ks = 0; ks < 16; ks += 8) {
            uint32_t a[2][4];
            #pragma unroll
            for (int mf = 0; mf < 2; mf++) {
                int m0 = m_base + mf * 16 + gid;
                a[mf][0] = __float_as_uint(As[lb][ks + tig][m0]);
                a[mf][1] = __float_as_uint(As[lb][ks + tig][m0 + 8]);
                a[mf][2] = __float_as_uint(As[lb][ks + tig + 4][m0]);
                a[mf][3] = __float_as_uint(As[lb][ks + tig + 4][m0 + 8]);
            }
            #pragma unroll
            for (int nf = 0; nf < 4; nf++) {
                int n0 = n_base + nf * 8 + gid;
                uint32_t b0 = __float_as_uint(Bs[lb][ks + tig][n0]);
                uint32_t b1 = __float_as_uint(Bs[lb][ks + tig + 4][n0]);
                mma_tf32(acc[0][nf], a[0], b0, b1);
                mma_tf32(acc[1][nf], a[1], b0, b1);
            }
        }
    }

    float* Ob = O + (size_t)b * SEQ * HID + h * HDIM + (size_t)bm * HID;
    #pragma unroll
    for (int mf = 0; mf < 2; mf++) {
        int r0 = m_base + mf * 16 + gid;
        #pragma unroll
        for (int nf = 0; nf < 4; nf++) {
            int col = n_base + nf * 8 + tig * 2;
            *(float2*)(Ob + (size_t)r0 * HID + col)       = make_float2(acc[mf][nf][0], acc[mf][nf][1]);
            *(float2*)(Ob + (size_t)(r0 + 8) * HID + col) = make_float2(acc[mf][nf][2], acc[mf][nf][3]);
        }
    }
}

// ---------------- launch ----------------
extern "C" void kernel_launch(void* const* d_in, const int* in_sizes, int n_in,
                              void* d_out, int out_size) {
    const float* hidden = (const float*)d_in[0];
    const float* ln1g = (const float*)d_in[1];
    const float* ln1b = (const float*)d_in[2];
    const float* Wq = (const float*)d_in[3];
    const float* bq = (const float*)d_in[4];
    const float* Wk = (const float*)d_in[5];
    const float* bk = (const float*)d_in[6];
    const float* Wv = (const float*)d_in[7];
    const float* bv = (const float*)d_in[8];
    const float* Wo = (const float*)d_in[9];
    const float* bo = (const float*)d_in[10];
    const float* lam = (const float*)d_in[11];
    const float* ln2g = (const float*)d_in[12];
    const float* ln2b = (const float*)d_in[13];
    const float* W1 = (const float*)d_in[14];
    const float* b1 = (const float*)d_in[15];
    const float* W2 = (const float*)d_in[16];
    const float* b2 = (const float*)d_in[17];

    float* out0 = (float*)d_out;
    float* attn = out0 + (size_t)MTOT * HID;  // [B,NH,S,S] follows [B,S,H]

    float *x, *q, *k, *v, *ao, *r1, *y, *ff;
    cudaGetSymbolAddress((void**)&x,  g_x);
    cudaGetSymbolAddress((void**)&q,  g_q);
    cudaGetSymbolAddress((void**)&k,  g_k);
    cudaGetSymbolAddress((void**)&v,  g_v);
    cudaGetSymbolAddress((void**)&ao, g_ao);
    cudaGetSymbolAddress((void**)&r1, g_r1);
    cudaGetSymbolAddress((void**)&y,  g_y);
    cudaGetSymbolAddress((void**)&ff, g_ff);

    float* pS = y + PS_OFF;

    int epiGrid = (MTOT * HID) / (256 * 4);   // 1536

    ln_kernel<<<MTOT, 256>>>(hidden, ln1g, ln1b, x);
    qkv_kernel<<<dim3(18, 16), 256>>>(x, Wq, Wk, Wv, bq, bk, bv, q, k, v);
    dist_kernel<<<dim3(SEQ / 64, SEQ / 128, BHTOT), 256>>>(q, k, lam, attn, pS);
    pv_kernel<<<dim3(SEQ / 128, 1, BHTOT), 256>>>(attn, v, pS, ao);
    // Wo with split-K=2: partials in g_x (x free) and g_ff (free until FF1)
    gemm_split_kernel<<<dim3(6, 16, 2), 256>>>(ao, HID, Wo, HID, x, ff);
    epi_kernel<<<epiGrid, 256>>>(x, ff, bo, hidden, r1);
    ln_kernel<<<MTOT, 256>>>(r1, ln2g, ln2b, y);   // overwrites pS (already consumed)
    gemm_kernel<<<dim3(24, 16), 256>>>(y, HID, W1, FFD, b1, ff, 2);          // gelu (N=3072)
    // FF2 with split-K=2: partials in g_x and g_q (both free now)
    gemm_split_kernel<<<dim3(6, 16, 2), 256>>>(ff, FFD, W2, HID, x, q);
    epi_kernel<<<epiGrid, 256>>>(x, q, b2, r1, out0);
}

// round 15
// speedup vs baseline: 1.0988x; 1.0385x over previous
#include <cuda_runtime.h>
#include <math.h>
#include <stdint.h>

#define SEQ   1024
#define BATCH 2
#define HID   768
#define NHEAD 12
#define HDIM  64
#define FFD   3072
#define MTOT  (BATCH*SEQ)   // 2048
#define BHTOT (BATCH*NHEAD) // 24

#define APAD 136
#define BPAD 72
#define BPAD2 136
#define APD64 72   // 64-row A tile pad: 72 % 32 == 8 -> conflict-free fragment loads

// ---------------- scratch (device globals: no allocation allowed) ----------------
__device__ float g_x [MTOT*HID];
__device__ float g_q [MTOT*HID];
__device__ float g_k [MTOT*HID];
__device__ float g_v [MTOT*HID];
__device__ float g_ao[MTOT*HID];
__device__ float g_r1[MTOT*HID];
__device__ float g_y [MTOT*HID];   // hosts softmax partial sums before ln2 reuses it
__device__ float g_ff[MTOT*FFD];

#define PS_OFF   0   // 24576 rows x 16 tile-sums inside g_y

// ---------------- helpers ----------------
__device__ __forceinline__ unsigned long long f2add(unsigned long long a, unsigned long long b) {
    unsigned long long r;
    asm("add.rn.f32x2 %0, %1, %2;" : "=l"(r) : "l"(a), "l"(b));
    return r;
}

__device__ __forceinline__ float gelu1(float v) {
    return 0.5f * v * (1.f + erff(v * 0.70710678118654752f));
}

__device__ __forceinline__ float to_tf32(float x) {
    uint32_t u;
    asm("cvt.rna.tf32.f32 %0, %1;" : "=r"(u) : "f"(x));
    return __uint_as_float(u);
}

__device__ __forceinline__ void mma_tf32(float (&c)[4], const uint32_t (&a)[4],
                                         uint32_t b0, uint32_t b1) {
    asm("mma.sync.aligned.m16n8k8.row.col.f32.tf32.tf32.f32 "
        "{%0,%1,%2,%3}, {%4,%5,%6,%7}, {%8,%9}, {%0,%1,%2,%3};"
        : "+f"(c[0]), "+f"(c[1]), "+f"(c[2]), "+f"(c[3])
        : "r"(a[0]), "r"(a[1]), "r"(a[2]), "r"(a[3]), "r"(b0), "r"(b1));
}

// ---------------- LayerNorm: one block per row of 768 ----------------
__global__ void ln_kernel(const float* __restrict__ in, const float* __restrict__ g,
                          const float* __restrict__ b, float* __restrict__ out) {
    int row = blockIdx.x;
    const float* x = in + (size_t)row * HID;
    int t = threadIdx.x;
    float v0 = x[t], v1 = x[t + 256], v2 = x[t + 512];
    float s  = v0 + v1 + v2;
    float sq = v0 * v0 + v1 * v1 + v2 * v2;
    __shared__ float sh[16];
    #pragma unroll
    for (int o = 16; o; o >>= 1) {
        s  += __shfl_xor_sync(0xffffffffu, s,  o);
        sq += __shfl_xor_sync(0xffffffffu, sq, o);
    }
    int w = t >> 5, l = t & 31;
    if (!l) { sh[w] = s; sh[w + 8] = sq; }
    __syncthreads();
    if (w == 0) {
        float a = (l < 8) ? sh[l] : 0.f;
        float c = (l < 8) ? sh[l + 8] : 0.f;
        #pragma unroll
        for (int o = 4; o; o >>= 1) {
            a += __shfl_xor_sync(0xffffffffu, a, o);
            c += __shfl_xor_sync(0xffffffffu, c, o);
        }
        if (!l) { sh[0] = a; sh[1] = c; }
    }
    __syncthreads();
    float mean = sh[0] * (1.f / HID);
    float var  = sh[1] * (1.f / HID) - mean * mean;
    float rs   = rsqrtf(var + 1e-5f);
    float* o = out + (size_t)row * HID;
    o[t]       = (v0 - mean) * rs * g[t]       + b[t];
    o[t + 256] = (v1 - mean) * rs * g[t + 256] + b[t + 256];
    o[t + 512] = (v2 - mean) * rs * g[t + 512] + b[t + 512];
}

// ======================= tf32 128x128 engine (qkv / Wo / FF) =======================
__device__ __forceinline__ void mma_compute128(
    const float (*Ab)[APAD], const float (*Bb)[BPAD2],
    int m_base, int n_base, int gid, int tig, float (&acc)[4][4][4])
{
    #pragma unroll
    for (int ks = 0; ks < 16; ks += 8) {
        uint32_t a[4][4];
        #pragma unroll
        for (int mf = 0; mf < 4; mf++) {
            int m0 = m_base + mf * 16 + gid;
            a[mf][0] = __float_as_uint(Ab[ks + tig][m0]);
            a[mf][1] = __float_as_uint(Ab[ks + tig][m0 + 8]);
            a[mf][2] = __float_as_uint(Ab[ks + tig + 4][m0]);
            a[mf][3] = __float_as_uint(Ab[ks + tig + 4][m0 + 8]);
        }
        #pragma unroll
        for (int nf = 0; nf < 4; nf++) {
            int n0 = n_base + nf * 8 + gid;
            uint32_t b0 = __float_as_uint(Bb[ks + tig][n0]);
            uint32_t b1 = __float_as_uint(Bb[ks + tig + 4][n0]);
            #pragma unroll
            for (int mf = 0; mf < 4; mf++)
                mma_tf32(acc[mf][nf], a[mf], b0, b1);
        }
    }
}

__device__ __forceinline__ void mma_tile128(
    const float* __restrict__ A, int lda,
    const float* __restrict__ B, int ldb,
    int kLen,
    float (*As)[16][APAD], float (*Bs)[16][BPAD2],
    float (&acc)[4][4][4])
{
    int tid = threadIdx.x;
    int ar = tid >> 1, ac = (tid & 1) * 8;
    int br = tid >> 4, bc = (tid & 15) * 4;
    int lane = tid & 31, wid = tid >> 5;
    int gid = lane >> 2, tig = lane & 3;
    int m_base = (wid & 1) * 64, n_base = (wid >> 1) * 32;

    const float* Ap = A + (size_t)ar * lda + ac;
    const float* Bp = B + (size_t)br * ldb + bc;

    {
        float4 av0 = *(const float4*)(Ap);
        float4 av1 = *(const float4*)(Ap + 4);
        float4 bv0 = *(const float4*)(Bp);
        float4 bv1 = *(const float4*)(Bp + 64);
        As[0][ac + 0][ar] = to_tf32(av0.x); As[0][ac + 1][ar] = to_tf32(av0.y);
        As[0][ac + 2][ar] = to_tf32(av0.z); As[0][ac + 3][ar] = to_tf32(av0.w);
        As[0][ac + 4][ar] = to_tf32(av1.x); As[0][ac + 5][ar] = to_tf32(av1.y);
        As[0][ac + 6][ar] = to_tf32(av1.z); As[0][ac + 7][ar] = to_tf32(av1.w);
        float4 bt0 = make_float4(to_tf32(bv0.x), to_tf32(bv0.y), to_tf32(bv0.z), to_tf32(bv0.w));
        float4 bt1 = make_float4(to_tf32(bv1.x), to_tf32(bv1.y), to_tf32(bv1.z), to_tf32(bv1.w));
        *(float4*)&Bs[0][br][bc]      = bt0;
        *(float4*)&Bs[0][br][bc + 64] = bt1;
    }
    __syncthreads();

    int kc = kLen >> 4;
    for (int c = 1; c < kc; c++) {
        const float* Ac = Ap + c * 16;
        const float* Bc = Bp + (size_t)(c * 16) * ldb;
        float4 av0 = *(const float4*)(Ac);
        float4 av1 = *(const float4*)(Ac + 4);
        float4 bv0 = *(const float4*)(Bc);
        float4 bv1 = *(const float4*)(Bc + 64);
        int pb = (c - 1) & 1, nb = c & 1;
        mma_compute128(As[pb], Bs[pb], m_base, n_base, gid, tig, acc);
        As[nb][ac + 0][ar] = to_tf32(av0.x); As[nb][ac + 1][ar] = to_tf32(av0.y);
        As[nb][ac + 2][ar] = to_tf32(av0.z); As[nb][ac + 3][ar] = to_tf32(av0.w);
        As[nb][ac + 4][ar] = to_tf32(av1.x); As[nb][ac + 5][ar] = to_tf32(av1.y);
        As[nb][ac + 6][ar] = to_tf32(av1.z); As[nb][ac + 7][ar] = to_tf32(av1.w);
        float4 bt0 = make_float4(to_tf32(bv0.x), to_tf32(bv0.y), to_tf32(bv0.z), to_tf32(bv0.w));
        float4 bt1 = make_float4(to_tf32(bv1.x), to_tf32(bv1.y), to_tf32(bv1.z), to_tf32(bv1.w));
        *(float4*)&Bs[nb][br][bc]      = bt0;
        *(float4*)&Bs[nb][br][bc + 64] = bt1;
        __syncthreads();
    }
    int lb = (kc - 1) & 1;
    mma_compute128(As[lb], Bs[lb], m_base, n_base, gid, tig, acc);
}

// ---------------- fused QKV: grid (18,16); blockIdx.x/6 selects matrix ----------------
__global__ void __launch_bounds__(256, 2) qkv_kernel(
    const float* __restrict__ x,
    const float* __restrict__ Wq, const float* __restrict__ Wk, const float* __restrict__ Wv,
    const float* __restrict__ bq, const float* __restrict__ bk, const float* __restrict__ bv,
    float* __restrict__ q, float* __restrict__ k, float* __restrict__ v)
{
    __shared__ float As[2][16][APAD];
    __shared__ float Bs[2][16][BPAD2];
    int sel = blockIdx.x / 6;
    int bn  = (blockIdx.x % 6) * 128;
    int bm  = blockIdx.y * 128;
    const float* B    = sel == 0 ? Wq : (sel == 1 ? Wk : Wv);
    const float* bias = sel == 0 ? bq : (sel == 1 ? bk : bv);
    float* C          = sel == 0 ? q  : (sel == 1 ? k  : v);
    float acc[4][4][4] = {};
    mma_tile128(x + (size_t)bm * HID, HID, B + bn, HID, HID, As, Bs, acc);
    int tid = threadIdx.x, lane = tid & 31, wid = tid >> 5;
    int gid = lane >> 2, tig = lane & 3;
    int m_base = (wid & 1) * 64, n_base = (wid >> 1) * 32;
    #pragma unroll
    for (int mf = 0; mf < 4; mf++) {
        int r0 = bm + m_base + mf * 16 + gid;
        #pragma unroll
        for (int nf = 0; nf < 4; nf++) {
            int col = bn + n_base + nf * 8 + tig * 2;
            float2 bi = *(const float2*)(bias + col);
            *(float2*)(C + (size_t)r0 * HID + col) =
                make_float2(acc[mf][nf][0] + bi.x, acc[mf][nf][1] + bi.y);
            *(float2*)(C + (size_t)(r0 + 8) * HID + col) =
                make_float2(acc[mf][nf][2] + bi.x, acc[mf][nf][3] + bi.y);
        }
    }
}

// ---------------- generic gemm: grid (N/128, M/128); mode 0=+bias 2=gelu(+bias) ----------------
__global__ void __launch_bounds__(256, 2) gemm_kernel(
    const float* __restrict__ A, int K,
    const float* __restrict__ B, int N,
    const float* __restrict__ bias,
    float* __restrict__ C, int mode)
{
    __shared__ float As[2][16][APAD];
    __shared__ float Bs[2][16][BPAD2];
    int bm = blockIdx.y * 128, bn = blockIdx.x * 128;
    float acc[4][4][4] = {};
    mma_tile128(A + (size_t)bm * K, K, B + bn, N, K, As, Bs, acc);
    int tid = threadIdx.x, lane = tid & 31, wid = tid >> 5;
    int gid = lane >> 2, tig = lane & 3;
    int m_base = (wid & 1) * 64, n_base = (wid >> 1) * 32;
    #pragma unroll
    for (int mf = 0; mf < 4; mf++) {
        int r0 = bm + m_base + mf * 16 + gid;
        #pragma unroll
        for (int nf = 0; nf < 4; nf++) {
            int col = bn + n_base + nf * 8 + tig * 2;
            float2 bi = *(const float2*)(bias + col);
            float o0 = acc[mf][nf][0] + bi.x, o1 = acc[mf][nf][1] + bi.y;
            float o2 = acc[mf][nf][2] + bi.x, o3 = acc[mf][nf][3] + bi.y;
            if (mode == 2) { o0 = gelu1(o0); o1 = gelu1(o1); o2 = gelu1(o2); o3 = gelu1(o3); }
            *(float2*)(C + (size_t)r0 * N + col)       = make_float2(o0, o1);
            *(float2*)(C + (size_t)(r0 + 8) * N + col) = make_float2(o2, o3);
        }
    }
}

// ---------------- split-K=2 gemm: grid (N/128, M/128, 2) -> raw partials ----------------
__global__ void __launch_bounds__(256, 2) gemm_split_kernel(
    const float* __restrict__ A, int K,
    const float* __restrict__ B, int N,
    float* __restrict__ P1, float* __restrict__ P2)
{
    __shared__ float As[2][16][APAD];
    __shared__ float Bs[2][16][BPAD2];
    int bm = blockIdx.y * 128, bn = blockIdx.x * 128;
    int half = K >> 1, z = blockIdx.z;
    float acc[4][4][4] = {};
    mma_tile128(A + (size_t)bm * K + z * half, K,
                B + (size_t)(z * half) * N + bn, N, half, As, Bs, acc);
    float* C = z ? P2 : P1;
    int tid = threadIdx.x, lane = tid & 31, wid = tid >> 5;
    int gid = lane >> 2, tig = lane & 3;
    int m_base = (wid & 1) * 64, n_base = (wid >> 1) * 32;
    #pragma unroll
    for (int mf = 0; mf < 4; mf++) {
        int r0 = bm + m_base + mf * 16 + gid;
        #pragma unroll
        for (int nf = 0; nf < 4; nf++) {
            int col = bn + n_base + nf * 8 + tig * 2;
            *(float2*)(C + (size_t)r0 * N + col)       = make_float2(acc[mf][nf][0], acc[mf][nf][1]);
            *(float2*)(C + (size_t)(r0 + 8) * N + col) = make_float2(acc[mf][nf][2], acc[mf][nf][3]);
        }
    }
}

// ---------------- epilogue: out = p1 + p2 + bias + res ----------------
__global__ void epi_kernel(const float* __restrict__ p1, const float* __restrict__ p2,
                           const float* __restrict__ bias, const float* __restrict__ res,
                           float* __restrict__ out)
{
    int idx = (blockIdx.x * 256 + threadIdx.x) * 4;
    int col = idx % HID;
    float4 a  = *(const float4*)(p1 + idx);
    float4 b  = *(const float4*)(p2 + idx);
    float4 r  = *(const float4*)(res + idx);
    float4 bi = *(const float4*)(bias + col);
    float4 o = make_float4(a.x + b.x + r.x + bi.x, a.y + b.y + r.y + bi.y,
                           a.z + b.z + r.z + bi.z, a.w + b.w + r.w + bi.w);
    *(float4*)(out + idx) = o;
}

// ---------------- L1 distance -> exp(score) + per-tile row sums ----------------
// Scores always <= 0, |score| << 87 -> exp without max-subtraction is exact.
__global__ void __launch_bounds__(256, 2) dist_kernel(
    const float* __restrict__ Q, const float* __restrict__ Km,
    const float* __restrict__ lamp, float* __restrict__ attn,
    float* __restrict__ pS)
{
    __shared__ unsigned long long Qs[32][128];   // [d-pair][q-row]
    __shared__ unsigned long long Ks[32][64];    // negated K
    int bh = blockIdx.z, b = bh / NHEAD, h = bh - b * NHEAD;
    int qbase = blockIdx.y * 128, kbase = blockIdx.x * 64;
    const float* Qb = Q  + (size_t)b * SEQ * HID + h * HDIM + (size_t)qbase * HID;
    const float* Kb = Km + (size_t)b * SEQ * HID + h * HDIM + (size_t)kbase * HID;
    int tid = threadIdx.x;

    union F2U { float2 f; unsigned long long u; };
    {
        int row = tid >> 1, hh = (tid & 1) * 32;
        #pragma unroll
        for (int i = 0; i < 8; i++) {
            float4 qv = *(const float4*)(Qb + (size_t)row * HID + hh + i * 4);
            F2U t;
            t.f = make_float2(qv.x, qv.y); Qs[(hh >> 1) + i * 2][row]     = t.u;
            t.f = make_float2(qv.z, qv.w); Qs[(hh >> 1) + i * 2 + 1][row] = t.u;
        }
    }
    {
        int row = tid >> 2, kq = (tid & 3) * 16;
        #pragma unroll
        for (int i = 0; i < 4; i++) {
            float4 kv = *(const float4*)(Kb + (size_t)row * HID + kq + i * 4);
            F2U t;
            t.f = make_float2(-kv.x, -kv.y); Ks[(kq >> 1) + i * 2][row]     = t.u;
            t.f = make_float2(-kv.z, -kv.w); Ks[(kq >> 1) + i * 2 + 1][row] = t.u;
        }
    }
    __syncthreads();

    int tx = tid & 15, ty = tid >> 4;
    int qs = ty * 8, ks = tx * 4;
    unsigned long long acc[8][4] = {};
    const unsigned long long MASK = 0x7FFFFFFF7FFFFFFFull;
    #pragma unroll 8
    for (int d = 0; d < 32; d++) {
        unsigned long long qv[8], kv[4];
        *(ulonglong2*)&qv[0] = *(const ulonglong2*)&Qs[d][qs];
        *(ulonglong2*)&qv[2] = *(const ulonglong2*)&Qs[d][qs + 2];
        *(ulonglong2*)&qv[4] = *(const ulonglong2*)&Qs[d][qs + 4];
        *(ulonglong2*)&qv[6] = *(const ulonglong2*)&Qs[d][qs + 6];
        *(ulonglong2*)&kv[0] = *(const ulonglong2*)&Ks[d][ks];
        *(ulonglong2*)&kv[2] = *(const ulonglong2*)&Ks[d][ks + 2];
        #pragma unroll
        for (int i = 0; i < 8; i++)
            #pragma unroll
            for (int j = 0; j < 4; j++) {
                unsigned long long df = f2add(qv[i], kv[j]) & MASK;
                acc[i][j] = f2add(acc[i][j], df);
            }
    }
    float c = -(*lamp) * 0.125f;   // scale = 1/sqrt(64)
    float* outp = attn + (size_t)bh * SEQ * SEQ + (size_t)(qbase + qs) * SEQ + kbase + ks;
    size_t srow = ((size_t)bh * SEQ + qbase + qs) * 16 + blockIdx.x;
    #pragma unroll
    for (int i = 0; i < 8; i++) {
        F2U t;
        float e0, e1, e2, e3;
        t.u = acc[i][0]; e0 = __expf(c * (t.f.x + t.f.y));
        t.u = acc[i][1]; e1 = __expf(c * (t.f.x + t.f.y));
        t.u = acc[i][2]; e2 = __expf(c * (t.f.x + t.f.y));
        t.u = acc[i][3]; e3 = __expf(c * (t.f.x + t.f.y));
        *(float4*)(outp + (size_t)i * SEQ) = make_float4(e0, e1, e2, e3);
        float s = e0 + e1 + e2 + e3;
        #pragma unroll
        for (int o = 8; o; o >>= 1) s += __shfl_xor_sync(0xffffffffu, s, o);
        if (tx == 0) pS[srow + (size_t)i * 16] = s;
    }
}

// ---------------- fused stats-fold + normalize + attn write + attn@V ----------------
// BM=64 tile -> grid (16,1,24)=384 blocks for real multi-CTA occupancy.
__global__ void __launch_bounds__(256, 4) pv_kernel(
    float* __restrict__ attn, const float* __restrict__ V,
    const float* __restrict__ pS, float* __restrict__ O)
{
    __shared__ float As[2][16][APD64];
    __shared__ float Bs[2][16][BPAD];
    __shared__ float smI[64];
    int bh = blockIdx.z, b = bh / NHEAD, h = bh - b * NHEAD;
    int bm = blockIdx.x * 64;
    float* A        = attn + (size_t)bh * SEQ * SEQ + (size_t)bm * SEQ;
    const float* Bv = V + (size_t)b * SEQ * HID + h * HDIM;
    int tid = threadIdx.x;
    if (tid < 64) {
        const float* s16 = pS + ((size_t)bh * SEQ + bm + tid) * 16;
        float s = 0.f;
        #pragma unroll
        for (int j = 0; j < 16; j += 4) {
            float4 a4 = *(const float4*)(s16 + j);
            s += a4.x + a4.y + a4.z + a4.w;
        }
        smI[tid] = 1.f / s;
    }
    __syncthreads();

    int ar = tid >> 2, ac = (tid & 3) * 4;       // A: 64 rows x 16 cols, 4 floats/thread
    int br = tid >> 4, bc = (tid & 15) * 4;      // V: 16 rows x 64 cols
    int lane = tid & 31, wid = tid >> 5;
    int gid = lane >> 2, tig = lane & 3;
    int m_base = (wid & 1) * 32, n_base = (wid >> 1) * 16;
    float rowI = smI[ar];
    float acc[2][2][4] = {};

    float* Ap       = A + (size_t)ar * SEQ + ac;
    const float* Bp = Bv + (size_t)br * HID + bc;

    {   // chunk 0: load exp, normalize (FMUL), write back, stage tf32
        float4 a0 = *(const float4*)(Ap);
        float4 bv = *(const float4*)(Bp);
        float n0 = a0.x * rowI, n1 = a0.y * rowI, n2 = a0.z * rowI, n3 = a0.w * rowI;
        *(float4*)(Ap) = make_float4(n0, n1, n2, n3);
        As[0][ac + 0][ar] = to_tf32(n0); As[0][ac + 1][ar] = to_tf32(n1);
        As[0][ac + 2][ar] = to_tf32(n2); As[0][ac + 3][ar] = to_tf32(n3);
        float4 bt = make_float4(to_tf32(bv.x), to_tf32(bv.y), to_tf32(bv.z), to_tf32(bv.w));
        *(float4*)&Bs[0][br][bc] = bt;
    }
    __syncthreads();

    for (int c = 1; c < SEQ / 16; c++) {
        float* Ac = Ap + c * 16;
        float4 a0 = *(const float4*)(Ac);
        float4 bv = *(const float4*)(Bp + (size_t)(c * 16) * HID);
        int pb = (c - 1) & 1, nb = c & 1;
        #pragma unroll
        for (int ks = 0; ks < 16; ks += 8) {
            uint32_t a[2][4];
            #pragma unroll
            for (int mf = 0; mf < 2; mf++) {
                int m0 = m_base + mf * 16 + gid;
                a[mf][0] = __float_as_uint(As[pb][ks + tig][m0]);
                a[mf][1] = __float_as_uint(As[pb][ks + tig][m0 + 8]);
                a[mf][2] = __float_as_uint(As[pb][ks + tig + 4][m0]);
                a[mf][3] = __float_as_uint(As[pb][ks + tig + 4][m0 + 8]);
            }
            #pragma unroll
            for (int nf = 0; nf < 2; nf++) {
                int n0 = n_base + nf * 8 + gid;
                uint32_t b0 = __float_as_uint(Bs[pb][ks + tig][n0]);
                uint32_t b1 = __float_as_uint(Bs[pb][ks + tig + 4][n0]);
                mma_tf32(acc[0][nf], a[0], b0, b1);
                mma_tf32(acc[1][nf], a[1], b0, b1);
            }
        }
        float n0 = a0.x * rowI, n1 = a0.y * rowI, n2 = a0.z * rowI, n3 = a0.w * rowI;
        *(float4*)(Ac) = make_float4(n0, n1, n2, n3);
        As[nb][ac + 0][ar] = to_tf32(n0); As[nb][ac + 1][ar] = to_tf32(n1);
        As[nb][ac + 2][ar] = to_tf32(n2); As[nb][ac + 3][ar] = to_tf32(n3);
        float4 bt = make_float4(to_tf32(bv.x), to_tf32(bv.y), to_tf32(bv.z), to_tf32(bv.w));
        *(float4*)&Bs[nb][br][bc] = bt;
        __syncthreads();
    }
    {   // last chunk compute
        int lb = (SEQ / 16 - 1) & 1;
        #pragma unroll
        for (int ks = 0; ks < 16; ks += 8) {
            uint32_t a[2][4];
            #pragma unroll
            for (int mf = 0; mf < 2; mf++) {
                int m0 = m_base + mf * 16 + gid;
                a[mf][0] = __float_as_uint(As[lb][ks + tig][m0]);
                a[mf][1] = __float_as_uint(As[lb][ks + tig][m0 + 8]);
                a[mf][2] = __float_as_uint(As[lb][ks + tig + 4][m0]);
                a[mf][3] = __float_as_uint(As[lb][ks + tig + 4][m0 + 8]);
            }
            #pragma unroll
            for (int nf = 0; nf < 2; nf++) {
                int n0 = n_base + nf * 8 + gid;
                uint32_t b0 = __float_as_uint(Bs[lb][ks + tig][n0]);
                uint32_t b1 = __float_as_uint(Bs[lb][ks + tig + 4][n0]);
                mma_tf32(acc[0][nf], a[0], b0, b1);
                mma_tf32(acc[1][nf], a[1], b0, b1);
            }
        }
    }

    float* Ob = O + (size_t)b * SEQ * HID + h * HDIM + (size_t)bm * HID;
    #pragma unroll
    for (int mf = 0; mf < 2; mf++) {
        int r0 = m_base + mf * 16 + gid;
        #pragma unroll
        for (int nf = 0; nf < 2; nf++) {
            int col = n_base + nf * 8 + tig * 2;
            *(float2*)(Ob + (size_t)r0 * HID + col)       = make_float2(acc[mf][nf][0], acc[mf][nf][1]);
            *(float2*)(Ob + (size_t)(r0 + 8) * HID + col) = make_float2(acc[mf][nf][2], acc[mf][nf][3]);
        }
    }
}

// ---------------- launch ----------------
extern "C" void kernel_launch(void* const* d_in, const int* in_sizes, int n_in,
                              void* d_out, int out_size) {
    const float* hidden = (const float*)d_in[0];
    const float* ln1g = (const float*)d_in[1];
    const float* ln1b = (const float*)d_in[2];
    const float* Wq = (const float*)d_in[3];
    const float* bq = (const float*)d_in[4];
    const float* Wk = (const float*)d_in[5];
    const float* bk = (const float*)d_in[6];
    const float* Wv = (const float*)d_in[7];
    const float* bv = (const float*)d_in[8];
    const float* Wo = (const float*)d_in[9];
    const float* bo = (const float*)d_in[10];
    const float* lam = (const float*)d_in[11];
    const float* ln2g = (const float*)d_in[12];
    const float* ln2b = (const float*)d_in[13];
    const float* W1 = (const float*)d_in[14];
    const float* b1 = (const float*)d_in[15];
    const float* W2 = (const float*)d_in[16];
    const float* b2 = (const float*)d_in[17];

    float* out0 = (float*)d_out;
    float* attn = out0 + (size_t)MTOT * HID;  // [B,NH,S,S] follows [B,S,H]

    float *x, *q, *k, *v, *ao, *r1, *y, *ff;
    cudaGetSymbolAddress((void**)&x,  g_x);
    cudaGetSymbolAddress((void**)&q,  g_q);
    cudaGetSymbolAddress((void**)&k,  g_k);
    cudaGetSymbolAddress((void**)&v,  g_v);
    cudaGetSymbolAddress((void**)&ao, g_ao);
    cudaGetSymbolAddress((void**)&r1, g_r1);
    cudaGetSymbolAddress((void**)&y,  g_y);
    cudaGetSymbolAddress((void**)&ff, g_ff);

    float* pS = y + PS_OFF;

    int epiGrid = (MTOT * HID) / (256 * 4);   // 1536

    ln_kernel<<<MTOT, 256>>>(hidden, ln1g, ln1b, x);
    qkv_kernel<<<dim3(18, 16), 256>>>(x, Wq, Wk, Wv, bq, bk, bv, q, k, v);
    dist_kernel<<<dim3(SEQ / 64, SEQ / 128, BHTOT), 256>>>(q, k, lam, attn, pS);
    pv_kernel<<<dim3(SEQ / 64, 1, BHTOT), 256>>>(attn, v, pS, ao);
    // Wo with split-K=2: partials in g_x (x free) and g_ff (free until FF1)
    gemm_split_kernel<<<dim3(6, 16, 2), 256>>>(ao, HID, Wo, HID, x, ff);
    epi_kernel<<<epiGrid, 256>>>(x, ff, bo, hidden, r1);
    ln_kernel<<<MTOT, 256>>>(r1, ln2g, ln2b, y);   // overwrites pS (already consumed)
    gemm_kernel<<<dim3(24, 16), 256>>>(y, HID, W1, FFD, b1, ff, 2);          // gelu (N=3072)
    // FF2 with split-K=2: partials in g_x and g_q (both free now)
    gemm_split_kernel<<<dim3(6, 16, 2), 256>>>(ff, FFD, W2, HID, x, q);
    epi_kernel<<<epiGrid, 256>>>(x, q, b2, r1, out0);
}

// round 16
// speedup vs baseline: 1.1016x; 1.0026x over previous
#include <cuda_runtime.h>
#include <math.h>
#include <stdint.h>

#define SEQ   1024
#define BATCH 2
#define HID   768
#define NHEAD 12
#define HDIM  64
#define FFD   3072
#define MTOT  (BATCH*SEQ)   // 2048
#define BHTOT (BATCH*NHEAD) // 24

#define APAD 136
#define BPAD 72
#define BPAD2 136
#define APD32 40   // 32-row A tile pad: banks (8*(k)+m) mod 32 distinct per fragment load

// ---------------- scratch (device globals: no allocation allowed) ----------------
__device__ float g_x [MTOT*HID];
__device__ float g_q [MTOT*HID];
__device__ float g_k [MTOT*HID];
__device__ float g_v [MTOT*HID];
__device__ float g_ao[MTOT*HID];
__device__ float g_r1[MTOT*HID];
__device__ float g_y [MTOT*HID];   // hosts softmax partial sums before ln2 reuses it
__device__ float g_ff[MTOT*FFD];

#define PS_OFF   0   // 24576 rows x 16 tile-sums inside g_y

// ---------------- helpers ----------------
__device__ __forceinline__ unsigned long long f2add(unsigned long long a, unsigned long long b) {
    unsigned long long r;
    asm("add.rn.f32x2 %0, %1, %2;" : "=l"(r) : "l"(a), "l"(b));
    return r;
}

__device__ __forceinline__ float gelu1(float v) {
    return 0.5f * v * (1.f + erff(v * 0.70710678118654752f));
}

__device__ __forceinline__ float to_tf32(float x) {
    uint32_t u;
    asm("cvt.rna.tf32.f32 %0, %1;" : "=r"(u) : "f"(x));
    return __uint_as_float(u);
}

__device__ __forceinline__ void mma_tf32(float (&c)[4], const uint32_t (&a)[4],
                                         uint32_t b0, uint32_t b1) {
    asm("mma.sync.aligned.m16n8k8.row.col.f32.tf32.tf32.f32 "
        "{%0,%1,%2,%3}, {%4,%5,%6,%7}, {%8,%9}, {%0,%1,%2,%3};"
        : "+f"(c[0]), "+f"(c[1]), "+f"(c[2]), "+f"(c[3])
        : "r"(a[0]), "r"(a[1]), "r"(a[2]), "r"(a[3]), "r"(b0), "r"(b1));
}

// ---------------- LayerNorm: one block per row of 768 ----------------
__global__ void ln_kernel(const float* __restrict__ in, const float* __restrict__ g,
                          const float* __restrict__ b, float* __restrict__ out) {
    int row = blockIdx.x;
    const float* x = in + (size_t)row * HID;
    int t = threadIdx.x;
    float v0 = x[t], v1 = x[t + 256], v2 = x[t + 512];
    float s  = v0 + v1 + v2;
    float sq = v0 * v0 + v1 * v1 + v2 * v2;
    __shared__ float sh[16];
    #pragma unroll
    for (int o = 16; o; o >>= 1) {
        s  += __shfl_xor_sync(0xffffffffu, s,  o);
        sq += __shfl_xor_sync(0xffffffffu, sq, o);
    }
    int w = t >> 5, l = t & 31;
    if (!l) { sh[w] = s; sh[w + 8] = sq; }
    __syncthreads();
    if (w == 0) {
        float a = (l < 8) ? sh[l] : 0.f;
        float c = (l < 8) ? sh[l + 8] : 0.f;
        #pragma unroll
        for (int o = 4; o; o >>= 1) {
            a += __shfl_xor_sync(0xffffffffu, a, o);
            c += __shfl_xor_sync(0xffffffffu, c, o);
        }
        if (!l) { sh[0] = a; sh[1] = c; }
    }
    __syncthreads();
    float mean = sh[0] * (1.f / HID);
    float var  = sh[1] * (1.f / HID) - mean * mean;
    float rs   = rsqrtf(var + 1e-5f);
    float* o = out + (size_t)row * HID;
    o[t]       = (v0 - mean) * rs * g[t]       + b[t];
    o[t + 256] = (v1 - mean) * rs * g[t + 256] + b[t + 256];
    o[t + 512] = (v2 - mean) * rs * g[t + 512] + b[t + 512];
}

// ======================= tf32 128x128 engine (qkv / Wo / FF) =======================
__device__ __forceinline__ void mma_compute128(
    const float (*Ab)[APAD], const float (*Bb)[BPAD2],
    int m_base, int n_base, int gid, int tig, float (&acc)[4][4][4])
{
    #pragma unroll
    for (int ks = 0; ks < 16; ks += 8) {
        uint32_t a[4][4];
        #pragma unroll
        for (int mf = 0; mf < 4; mf++) {
            int m0 = m_base + mf * 16 + gid;
            a[mf][0] = __float_as_uint(Ab[ks + tig][m0]);
            a[mf][1] = __float_as_uint(Ab[ks + tig][m0 + 8]);
            a[mf][2] = __float_as_uint(Ab[ks + tig + 4][m0]);
            a[mf][3] = __float_as_uint(Ab[ks + tig + 4][m0 + 8]);
        }
        #pragma unroll
        for (int nf = 0; nf < 4; nf++) {
            int n0 = n_base + nf * 8 + gid;
            uint32_t b0 = __float_as_uint(Bb[ks + tig][n0]);
            uint32_t b1 = __float_as_uint(Bb[ks + tig + 4][n0]);
            #pragma unroll
            for (int mf = 0; mf < 4; mf++)
                mma_tf32(acc[mf][nf], a[mf], b0, b1);
        }
    }
}

__device__ __forceinline__ void mma_tile128(
    const float* __restrict__ A, int lda,
    const float* __restrict__ B, int ldb,
    int kLen,
    float (*As)[16][APAD], float (*Bs)[16][BPAD2],
    float (&acc)[4][4][4])
{
    int tid = threadIdx.x;
    int ar = tid >> 1, ac = (tid & 1) * 8;
    int br = tid >> 4, bc = (tid & 15) * 4;
    int lane = tid & 31, wid = tid >> 5;
    int gid = lane >> 2, tig = lane & 3;
    int m_base = (wid & 1) * 64, n_base = (wid >> 1) * 32;

    const float* Ap = A + (size_t)ar * lda + ac;
    const float* Bp = B + (size_t)br * ldb + bc;

    {
        float4 av0 = *(const float4*)(Ap);
        float4 av1 = *(const float4*)(Ap + 4);
        float4 bv0 = *(const float4*)(Bp);
        float4 bv1 = *(const float4*)(Bp + 64);
        As[0][ac + 0][ar] = to_tf32(av0.x); As[0][ac + 1][ar] = to_tf32(av0.y);
        As[0][ac + 2][ar] = to_tf32(av0.z); As[0][ac + 3][ar] = to_tf32(av0.w);
        As[0][ac + 4][ar] = to_tf32(av1.x); As[0][ac + 5][ar] = to_tf32(av1.y);
        As[0][ac + 6][ar] = to_tf32(av1.z); As[0][ac + 7][ar] = to_tf32(av1.w);
        float4 bt0 = make_float4(to_tf32(bv0.x), to_tf32(bv0.y), to_tf32(bv0.z), to_tf32(bv0.w));
        float4 bt1 = make_float4(to_tf32(bv1.x), to_tf32(bv1.y), to_tf32(bv1.z), to_tf32(bv1.w));
        *(float4*)&Bs[0][br][bc]      = bt0;
        *(float4*)&Bs[0][br][bc + 64] = bt1;
    }
    __syncthreads();

    int kc = kLen >> 4;
    for (int c = 1; c < kc; c++) {
        const float* Ac = Ap + c * 16;
        const float* Bc = Bp + (size_t)(c * 16) * ldb;
        float4 av0 = *(const float4*)(Ac);
        float4 av1 = *(const float4*)(Ac + 4);
        float4 bv0 = *(const float4*)(Bc);
        float4 bv1 = *(const float4*)(Bc + 64);
        int pb = (c - 1) & 1, nb = c & 1;
        mma_compute128(As[pb], Bs[pb], m_base, n_base, gid, tig, acc);
        As[nb][ac + 0][ar] = to_tf32(av0.x); As[nb][ac + 1][ar] = to_tf32(av0.y);
        As[nb][ac + 2][ar] = to_tf32(av0.z); As[nb][ac + 3][ar] = to_tf32(av0.w);
        As[nb][ac + 4][ar] = to_tf32(av1.x); As[nb][ac + 5][ar] = to_tf32(av1.y);
        As[nb][ac + 6][ar] = to_tf32(av1.z); As[nb][ac + 7][ar] = to_tf32(av1.w);
        float4 bt0 = make_float4(to_tf32(bv0.x), to_tf32(bv0.y), to_tf32(bv0.z), to_tf32(bv0.w));
        float4 bt1 = make_float4(to_tf32(bv1.x), to_tf32(bv1.y), to_tf32(bv1.z), to_tf32(bv1.w));
        *(float4*)&Bs[nb][br][bc]      = bt0;
        *(float4*)&Bs[nb][br][bc + 64] = bt1;
        __syncthreads();
    }
    int lb = (kc - 1) & 1;
    mma_compute128(As[lb], Bs[lb], m_base, n_base, gid, tig, acc);
}

// ---------------- fused QKV: grid (18,16); blockIdx.x/6 selects matrix ----------------
__global__ void __launch_bounds__(256, 2) qkv_kernel(
    const float* __restrict__ x,
    const float* __restrict__ Wq, const float* __restrict__ Wk, const float* __restrict__ Wv,
    const float* __restrict__ bq, const float* __restrict__ bk, const float* __restrict__ bv,
    float* __restrict__ q, float* __restrict__ k, float* __restrict__ v)
{
    __shared__ float As[2][16][APAD];
    __shared__ float Bs[2][16][BPAD2];
    int sel = blockIdx.x / 6;
    int bn  = (blockIdx.x % 6) * 128;
    int bm  = blockIdx.y * 128;
    const float* B    = sel == 0 ? Wq : (sel == 1 ? Wk : Wv);
    const float* bias = sel == 0 ? bq : (sel == 1 ? bk : bv);
    float* C          = sel == 0 ? q  : (sel == 1 ? k  : v);
    float acc[4][4][4] = {};
    mma_tile128(x + (size_t)bm * HID, HID, B + bn, HID, HID, As, Bs, acc);
    int tid = threadIdx.x, lane = tid & 31, wid = tid >> 5;
    int gid = lane >> 2, tig = lane & 3;
    int m_base = (wid & 1) * 64, n_base = (wid >> 1) * 32;
    #pragma unroll
    for (int mf = 0; mf < 4; mf++) {
        int r0 = bm + m_base + mf * 16 + gid;
        #pragma unroll
        for (int nf = 0; nf < 4; nf++) {
            int col = bn + n_base + nf * 8 + tig * 2;
            float2 bi = *(const float2*)(bias + col);
            *(float2*)(C + (size_t)r0 * HID + col) =
                make_float2(acc[mf][nf][0] + bi.x, acc[mf][nf][1] + bi.y);
            *(float2*)(C + (size_t)(r0 + 8) * HID + col) =
                make_float2(acc[mf][nf][2] + bi.x, acc[mf][nf][3] + bi.y);
        }
    }
}

// ---------------- generic gemm: grid (N/128, M/128); mode 0=+bias 2=gelu(+bias) ----------------
__global__ void __launch_bounds__(256, 2) gemm_kernel(
    const float* __restrict__ A, int K,
    const float* __restrict__ B, int N,
    const float* __restrict__ bias,
    float* __restrict__ C, int mode)
{
    __shared__ float As[2][16][APAD];
    __shared__ float Bs[2][16][BPAD2];
    int bm = blockIdx.y * 128, bn = blockIdx.x * 128;
    float acc[4][4][4] = {};
    mma_tile128(A + (size_t)bm * K, K, B + bn, N, K, As, Bs, acc);
    int tid = threadIdx.x, lane = tid & 31, wid = tid >> 5;
    int gid = lane >> 2, tig = lane & 3;
    int m_base = (wid & 1) * 64, n_base = (wid >> 1) * 32;
    #pragma unroll
    for (int mf = 0; mf < 4; mf++) {
        int r0 = bm + m_base + mf * 16 + gid;
        #pragma unroll
        for (int nf = 0; nf < 4; nf++) {
            int col = bn + n_base + nf * 8 + tig * 2;
            float2 bi = *(const float2*)(bias + col);
            float o0 = acc[mf][nf][0] + bi.x, o1 = acc[mf][nf][1] + bi.y;
            float o2 = acc[mf][nf][2] + bi.x, o3 = acc[mf][nf][3] + bi.y;
            if (mode == 2) { o0 = gelu1(o0); o1 = gelu1(o1); o2 = gelu1(o2); o3 = gelu1(o3); }
            *(float2*)(C + (size_t)r0 * N + col)       = make_float2(o0, o1);
            *(float2*)(C + (size_t)(r0 + 8) * N + col) = make_float2(o2, o3);
        }
    }
}

// ---------------- split-K=4 gemm: grid (N/128, M/128, 4) -> raw partials ----------------
__global__ void __launch_bounds__(256, 2) gemm_split4_kernel(
    const float* __restrict__ A, int K,
    const float* __restrict__ B, int N,
    float* __restrict__ P0, float* __restrict__ P1,
    float* __restrict__ P2, float* __restrict__ P3)
{
    __shared__ float As[2][16][APAD];
    __shared__ float Bs[2][16][BPAD2];
    int bm = blockIdx.y * 128, bn = blockIdx.x * 128;
    int quart = K >> 2, z = blockIdx.z;
    float acc[4][4][4] = {};
    mma_tile128(A + (size_t)bm * K + z * quart, K,
                B + (size_t)(z * quart) * N + bn, N, quart, As, Bs, acc);
    float* C = (z == 0) ? P0 : (z == 1) ? P1 : (z == 2) ? P2 : P3;
    int tid = threadIdx.x, lane = tid & 31, wid = tid >> 5;
    int gid = lane >> 2, tig = lane & 3;
    int m_base = (wid & 1) * 64, n_base = (wid >> 1) * 32;
    #pragma unroll
    for (int mf = 0; mf < 4; mf++) {
        int r0 = bm + m_base + mf * 16 + gid;
        #pragma unroll
        for (int nf = 0; nf < 4; nf++) {
            int col = bn + n_base + nf * 8 + tig * 2;
            *(float2*)(C + (size_t)r0 * N + col)       = make_float2(acc[mf][nf][0], acc[mf][nf][1]);
            *(float2*)(C + (size_t)(r0 + 8) * N + col) = make_float2(acc[mf][nf][2], acc[mf][nf][3]);
        }
    }
}

// ---------------- epilogue: out = p0 + p1 + p2 + p3 + bias + res ----------------
__global__ void epi4_kernel(const float* __restrict__ p0, const float* __restrict__ p1,
                            const float* __restrict__ p2, const float* __restrict__ p3,
                            const float* __restrict__ bias, const float* __restrict__ res,
                            float* __restrict__ out)
{
    int idx = (blockIdx.x * 256 + threadIdx.x) * 4;
    int col = idx % HID;
    float4 a  = *(const float4*)(p0 + idx);
    float4 b  = *(const float4*)(p1 + idx);
    float4 c  = *(const float4*)(p2 + idx);
    float4 d  = *(const float4*)(p3 + idx);
    float4 r  = *(const float4*)(res + idx);
    float4 bi = *(const float4*)(bias + col);
    float4 o = make_float4(a.x + b.x + c.x + d.x + r.x + bi.x,
                           a.y + b.y + c.y + d.y + r.y + bi.y,
                           a.z + b.z + c.z + d.z + r.z + bi.z,
                           a.w + b.w + c.w + d.w + r.w + bi.w);
    *(float4*)(out + idx) = o;
}

// ---------------- L1 distance -> exp(score) + per-tile row sums ----------------
// Scores always <= 0, |score| << 87 -> exp without max-subtraction is exact.
__global__ void __launch_bounds__(256, 2) dist_kernel(
    const float* __restrict__ Q, const float* __restrict__ Km,
    const float* __restrict__ lamp, float* __restrict__ attn,
    float* __restrict__ pS)
{
    __shared__ unsigned long long Qs[32][128];   // [d-pair][q-row]
    __shared__ unsigned long long Ks[32][64];    // negated K
    int bh = blockIdx.z, b = bh / NHEAD, h = bh - b * NHEAD;
    int qbase = blockIdx.y * 128, kbase = blockIdx.x * 64;
    const float* Qb = Q  + (size_t)b * SEQ * HID + h * HDIM + (size_t)qbase * HID;
    const float* Kb = Km + (size_t)b * SEQ * HID + h * HDIM + (size_t)kbase * HID;
    int tid = threadIdx.x;

    union F2U { float2 f; unsigned long long u; };
    {
        int row = tid >> 1, hh = (tid & 1) * 32;
        #pragma unroll
        for (int i = 0; i < 8; i++) {
            float4 qv = *(const float4*)(Qb + (size_t)row * HID + hh + i * 4);
            F2U t;
            t.f = make_float2(qv.x, qv.y); Qs[(hh >> 1) + i * 2][row]     = t.u;
            t.f = make_float2(qv.z, qv.w); Qs[(hh >> 1) + i * 2 + 1][row] = t.u;
        }
    }
    {
        int row = tid >> 2, kq = (tid & 3) * 16;
        #pragma unroll
        for (int i = 0; i < 4; i++) {
            float4 kv = *(const float4*)(Kb + (size_t)row * HID + kq + i * 4);
            F2U t;
            t.f = make_float2(-kv.x, -kv.y); Ks[(kq >> 1) + i * 2][row]     = t.u;
            t.f = make_float2(-kv.z, -kv.w); Ks[(kq >> 1) + i * 2 + 1][row] = t.u;
        }
    }
    __syncthreads();

    int tx = tid & 15, ty = tid >> 4;
    int qs = ty * 8, ks = tx * 4;
    unsigned long long acc[8][4] = {};
    const unsigned long long MASK = 0x7FFFFFFF7FFFFFFFull;
    #pragma unroll 8
    for (int d = 0; d < 32; d++) {
        unsigned long long qv[8], kv[4];
        *(ulonglong2*)&qv[0] = *(const ulonglong2*)&Qs[d][qs];
        *(ulonglong2*)&qv[2] = *(const ulonglong2*)&Qs[d][qs + 2];
        *(ulonglong2*)&qv[4] = *(const ulonglong2*)&Qs[d][qs + 4];
        *(ulonglong2*)&qv[6] = *(const ulonglong2*)&Qs[d][qs + 6];
        *(ulonglong2*)&kv[0] = *(const ulonglong2*)&Ks[d][ks];
        *(ulonglong2*)&kv[2] = *(const ulonglong2*)&Ks[d][ks + 2];
        #pragma unroll
        for (int i = 0; i < 8; i++)
            #pragma unroll
            for (int j = 0; j < 4; j++) {
                unsigned long long df = f2add(qv[i], kv[j]) & MASK;
                acc[i][j] = f2add(acc[i][j], df);
            }
    }
    float c = -(*lamp) * 0.125f;   // scale = 1/sqrt(64)
    float* outp = attn + (size_t)bh * SEQ * SEQ + (size_t)(qbase + qs) * SEQ + kbase + ks;
    size_t srow = ((size_t)bh * SEQ + qbase + qs) * 16 + blockIdx.x;
    #pragma unroll
    for (int i = 0; i < 8; i++) {
        F2U t;
        float e0, e1, e2, e3;
        t.u = acc[i][0]; e0 = __expf(c * (t.f.x + t.f.y));
        t.u = acc[i][1]; e1 = __expf(c * (t.f.x + t.f.y));
        t.u = acc[i][2]; e2 = __expf(c * (t.f.x + t.f.y));
        t.u = acc[i][3]; e3 = __expf(c * (t.f.x + t.f.y));
        *(float4*)(outp + (size_t)i * SEQ) = make_float4(e0, e1, e2, e3);
        float s = e0 + e1 + e2 + e3;
        #pragma unroll
        for (int o = 8; o; o >>= 1) s += __shfl_xor_sync(0xffffffffu, s, o);
        if (tx == 0) pS[srow + (size_t)i * 16] = s;
    }
}

// ---------------- fused stats-fold + normalize + attn write + attn@V ----------------
// BM=32 tile -> grid (32,1,24)=768 blocks; 8 warps as 2(m) x 4(n), warp tile 16x16.
__global__ void __launch_bounds__(256, 5) pv_kernel(
    float* __restrict__ attn, const float* __restrict__ V,
    const float* __restrict__ pS, float* __restrict__ O)
{
    __shared__ float As[2][16][APD32];
    __shared__ float Bs[2][16][BPAD];
    __shared__ float smI[32];
    int bh = blockIdx.z, b = bh / NHEAD, h = bh - b * NHEAD;
    int bm = blockIdx.x * 32;
    float* A        = attn + (size_t)bh * SEQ * SEQ + (size_t)bm * SEQ;
    const float* Bv = V + (size_t)b * SEQ * HID + h * HDIM;
    int tid = threadIdx.x;
    if (tid < 32) {
        const float* s16 = pS + ((size_t)bh * SEQ + bm + tid) * 16;
        float s = 0.f;
        #pragma unroll
        for (int j = 0; j < 16; j += 4) {
            float4 a4 = *(const float4*)(s16 + j);
            s += a4.x + a4.y + a4.z + a4.w;
        }
        smI[tid] = 1.f / s;
    }
    __syncthreads();

    bool aAct = tid < 128;
    int ar = tid >> 2, ac = (tid & 3) * 4;       // A: 32 rows x 16 cols (threads < 128)
    int br = tid >> 4, bc = (tid & 15) * 4;      // V: 16 rows x 64 cols (all threads)
    int lane = tid & 31, wid = tid >> 5;
    int gid = lane >> 2, tig = lane & 3;
    int m_base = (wid & 1) * 16, n_base = (wid >> 1) * 16;
    float rowI = aAct ? smI[ar] : 0.f;
    float acc[2][4] = {};   // nf=2

    float* Ap       = A + (size_t)ar * SEQ + ac;
    const float* Bp = Bv + (size_t)br * HID + bc;

    {   // chunk 0
        float4 bv = *(const float4*)(Bp);
        if (aAct) {
            float4 a0 = *(const float4*)(Ap);
            float n0 = a0.x * rowI, n1 = a0.y * rowI, n2 = a0.z * rowI, n3 = a0.w * rowI;
            *(float4*)(Ap) = make_float4(n0, n1, n2, n3);
            As[0][ac + 0][ar] = to_tf32(n0); As[0][ac + 1][ar] = to_tf32(n1);
            As[0][ac + 2][ar] = to_tf32(n2); As[0][ac + 3][ar] = to_tf32(n3);
        }
        float4 bt = make_float4(to_tf32(bv.x), to_tf32(bv.y), to_tf32(bv.z), to_tf32(bv.w));
        *(float4*)&Bs[0][br][bc] = bt;
    }
    __syncthreads();

    for (int c = 1; c < SEQ / 16; c++) {
        float* Ac = Ap + c * 16;
        float4 a0;
        if (aAct) a0 = *(const float4*)(Ac);
        float4 bv = *(const float4*)(Bp + (size_t)(c * 16) * HID);
        int pb = (c - 1) & 1, nb = c & 1;
        #pragma unroll
        for (int ks = 0; ks < 16; ks += 8) {
            uint32_t a[4];
            int m0 = m_base + gid;
            a[0] = __float_as_uint(As[pb][ks + tig][m0]);
            a[1] = __float_as_uint(As[pb][ks + tig][m0 + 8]);
            a[2] = __float_as_uint(As[pb][ks + tig + 4][m0]);
            a[3] = __float_as_uint(As[pb][ks + tig + 4][m0 + 8]);
            #pragma unroll
            for (int nf = 0; nf < 2; nf++) {
                int n0 = n_base + nf * 8 + gid;
                uint32_t b0 = __float_as_uint(Bs[pb][ks + tig][n0]);
                uint32_t b1 = __float_as_uint(Bs[pb][ks + tig + 4][n0]);
                mma_tf32(acc[nf], a, b0, b1);
            }
        }
        if (aAct) {
            float n0 = a0.x * rowI, n1 = a0.y * rowI, n2 = a0.z * rowI, n3 = a0.w * rowI;
            *(float4*)(Ac) = make_float4(n0, n1, n2, n3);
            As[nb][ac + 0][ar] = to_tf32(n0); As[nb][ac + 1][ar] = to_tf32(n1);
            As[nb][ac + 2][ar] = to_tf32(n2); As[nb][ac + 3][ar] = to_tf32(n3);
        }
        float4 bt = make_float4(to_tf32(bv.x), to_tf32(bv.y), to_tf32(bv.z), to_tf32(bv.w));
        *(float4*)&Bs[nb][br][bc] = bt;
        __syncthreads();
    }
    {   // last chunk compute
        int lb = (SEQ / 16 - 1) & 1;
        #pragma unroll
        for (int ks = 0; ks < 16; ks += 8) {
            uint32_t a[4];
            int m0 = m_base + gid;
            a[0] = __float_as_uint(As[lb][ks + tig][m0]);
            a[1] = __float_as_uint(As[lb][ks + tig][m0 + 8]);
            a[2] = __float_as_uint(As[lb][ks + tig + 4][m0]);
            a[3] = __float_as_uint(As[lb][ks + tig + 4][m0 + 8]);
            #pragma unroll
            for (int nf = 0; nf < 2; nf++) {
                int n0 = n_base + nf * 8 + gid;
                uint32_t b0 = __float_as_uint(Bs[lb][ks + tig][n0]);
                uint32_t b1 = __float_as_uint(Bs[lb][ks + tig + 4][n0]);
                mma_tf32(acc[nf], a, b0, b1);
            }
        }
    }

    float* Ob = O + (size_t)b * SEQ * HID + h * HDIM + (size_t)bm * HID;
    int r0 = m_base + gid;
    #pragma unroll
    for (int nf = 0; nf < 2; nf++) {
        int col = n_base + nf * 8 + tig * 2;
        *(float2*)(Ob + (size_t)r0 * HID + col)       = make_float2(acc[nf][0], acc[nf][1]);
        *(float2*)(Ob + (size_t)(r0 + 8) * HID + col) = make_float2(acc[nf][2], acc[nf][3]);
    }
}

// ---------------- launch ----------------
extern "C" void kernel_launch(void* const* d_in, const int* in_sizes, int n_in,
                              void* d_out, int out_size) {
    const float* hidden = (const float*)d_in[0];
    const float* ln1g = (const float*)d_in[1];
    const float* ln1b = (const float*)d_in[2];
    const float* Wq = (const float*)d_in[3];
    const float* bq = (const float*)d_in[4];
    const float* Wk = (const float*)d_in[5];
    const float* bk = (const float*)d_in[6];
    const float* Wv = (const float*)d_in[7];
    const float* bv = (const float*)d_in[8];
    const float* Wo = (const float*)d_in[9];
    const float* bo = (const float*)d_in[10];
    const float* lam = (const float*)d_in[11];
    const float* ln2g = (const float*)d_in[12];
    const float* ln2b = (const float*)d_in[13];
    const float* W1 = (const float*)d_in[14];
    const float* b1 = (const float*)d_in[15];
    const float* W2 = (const float*)d_in[16];
    const float* b2 = (const float*)d_in[17];

    float* out0 = (float*)d_out;
    float* attn = out0 + (size_t)MTOT * HID;  // [B,NH,S,S] follows [B,S,H]

    float *x, *q, *k, *v, *ao, *r1, *y, *ff;
    cudaGetSymbolAddress((void**)&x,  g_x);
    cudaGetSymbolAddress((void**)&q,  g_q);
    cudaGetSymbolAddress((void**)&k,  g_k);
    cudaGetSymbolAddress((void**)&v,  g_v);
    cudaGetSymbolAddress((void**)&ao, g_ao);
    cudaGetSymbolAddress((void**)&r1, g_r1);
    cudaGetSymbolAddress((void**)&y,  g_y);
    cudaGetSymbolAddress((void**)&ff, g_ff);

    float* pS = y + PS_OFF;

    int epiGrid = (MTOT * HID) / (256 * 4);   // 1536

    ln_kernel<<<MTOT, 256>>>(hidden, ln1g, ln1b, x);
    qkv_kernel<<<dim3(18, 16), 256>>>(x, Wq, Wk, Wv, bq, bk, bv, q, k, v);
    dist_kernel<<<dim3(SEQ / 64, SEQ / 128, BHTOT), 256>>>(q, k, lam, attn, pS);
    pv_kernel<<<dim3(SEQ / 32, 1, BHTOT), 256>>>(attn, v, pS, ao);
    // Wo with split-K=4: partials in x, q, k, ff (all dead here; ff consumed before FF1 writes it)
    gemm_split4_kernel<<<dim3(6, 16, 4), 256>>>(ao, HID, Wo, HID, x, q, k, ff);
    epi4_kernel<<<epiGrid, 256>>>(x, q, k, ff, bo, hidden, r1);
    ln_kernel<<<MTOT, 256>>>(r1, ln2g, ln2b, y);   // overwrites pS (already consumed)
    gemm_kernel<<<dim3(24, 16), 256>>>(y, HID, W1, FFD, b1, ff, 2);          // gelu (N=3072)
    // FF2 with split-K=4: partials in x, q, k, v (all dead now)
    gemm_split4_kernel<<<dim3(6, 16, 4), 256>>>(ff, FFD, W2, HID, x, q, k, v);
    epi4_kernel<<<epiGrid, 256>>>(x, q, k, v, b2, r1, out0);
}

// round 17
// speedup vs baseline: 1.1731x; 1.0648x over previous
#include <cuda_runtime.h>
#include <math.h>
#include <stdint.h>

#define SEQ   1024
#define BATCH 2
#define HID   768
#define NHEAD 12
#define HDIM  64
#define FFD   3072
#define MTOT  (BATCH*SEQ)   // 2048
#define BHTOT (BATCH*NHEAD) // 24

#define APAD 136
#define BPAD 72
#define BPAD2 136
#define APD64 72   // 64-row A tile pad: 72 % 32 == 8 -> conflict-free fragment loads

// ---------------- scratch (device globals: no allocation allowed) ----------------
__device__ float g_x [MTOT*HID];
__device__ float g_q [MTOT*HID];
__device__ float g_k [MTOT*HID];
__device__ float g_v [MTOT*HID];
__device__ float g_ao[MTOT*HID];
__device__ float g_r1[MTOT*HID];
__device__ float g_y [MTOT*HID];   // hosts softmax partial sums before ln2 reuses it
__device__ float g_ff[MTOT*FFD];

#define PS_OFF   0   // 24576 rows x 16 tile-sums inside g_y

// ---------------- helpers ----------------
__device__ __forceinline__ unsigned long long f2add(unsigned long long a, unsigned long long b) {
    unsigned long long r;
    asm("add.rn.f32x2 %0, %1, %2;" : "=l"(r) : "l"(a), "l"(b));
    return r;
}

__device__ __forceinline__ float gelu1(float v) {
    return 0.5f * v * (1.f + erff(v * 0.70710678118654752f));
}

__device__ __forceinline__ float to_tf32(float x) {
    uint32_t u;
    asm("cvt.rna.tf32.f32 %0, %1;" : "=r"(u) : "f"(x));
    return __uint_as_float(u);
}

__device__ __forceinline__ void mma_tf32(float (&c)[4], const uint32_t (&a)[4],
                                         uint32_t b0, uint32_t b1) {
    asm("mma.sync.aligned.m16n8k8.row.col.f32.tf32.tf32.f32 "
        "{%0,%1,%2,%3}, {%4,%5,%6,%7}, {%8,%9}, {%0,%1,%2,%3};"
        : "+f"(c[0]), "+f"(c[1]), "+f"(c[2]), "+f"(c[3])
        : "r"(a[0]), "r"(a[1]), "r"(a[2]), "r"(a[3]), "r"(b0), "r"(b1));
}

// ---------------- LayerNorm: one block per row of 768 ----------------
__global__ void ln_kernel(const float* __restrict__ in, const float* __restrict__ g,
                          const float* __restrict__ b, float* __restrict__ out) {
    int row = blockIdx.x;
    const float* x = in + (size_t)row * HID;
    int t = threadIdx.x;
    float v0 = x[t], v1 = x[t + 256], v2 = x[t + 512];
    float s  = v0 + v1 + v2;
    float sq = v0 * v0 + v1 * v1 + v2 * v2;
    __shared__ float sh[16];
    #pragma unroll
    for (int o = 16; o; o >>= 1) {
        s  += __shfl_xor_sync(0xffffffffu, s,  o);
        sq += __shfl_xor_sync(0xffffffffu, sq, o);
    }
    int w = t >> 5, l = t & 31;
    if (!l) { sh[w] = s; sh[w + 8] = sq; }
    __syncthreads();
    if (w == 0) {
        float a = (l < 8) ? sh[l] : 0.f;
        float c = (l < 8) ? sh[l + 8] : 0.f;
        #pragma unroll
        for (int o = 4; o; o >>= 1) {
            a += __shfl_xor_sync(0xffffffffu, a, o);
            c += __shfl_xor_sync(0xffffffffu, c, o);
        }
        if (!l) { sh[0] = a; sh[1] = c; }
    }
    __syncthreads();
    float mean = sh[0] * (1.f / HID);
    float var  = sh[1] * (1.f / HID) - mean * mean;
    float rs   = rsqrtf(var + 1e-5f);
    float* o = out + (size_t)row * HID;
    o[t]       = (v0 - mean) * rs * g[t]       + b[t];
    o[t + 256] = (v1 - mean) * rs * g[t + 256] + b[t + 256];
    o[t + 512] = (v2 - mean) * rs * g[t + 512] + b[t + 512];
}

// ======================= tf32 128x128 engine (qkv / Wo / FF) =======================
__device__ __forceinline__ void mma_compute128(
    const float (*Ab)[APAD], const float (*Bb)[BPAD2],
    int m_base, int n_base, int gid, int tig, float (&acc)[4][4][4])
{
    #pragma unroll
    for (int ks = 0; ks < 16; ks += 8) {
        uint32_t a[4][4];
        #pragma unroll
        for (int mf = 0; mf < 4; mf++) {
            int m0 = m_base + mf * 16 + gid;
            a[mf][0] = __float_as_uint(Ab[ks + tig][m0]);
            a[mf][1] = __float_as_uint(Ab[ks + tig][m0 + 8]);
            a[mf][2] = __float_as_uint(Ab[ks + tig + 4][m0]);
            a[mf][3] = __float_as_uint(Ab[ks + tig + 4][m0 + 8]);
        }
        #pragma unroll
        for (int nf = 0; nf < 4; nf++) {
            int n0 = n_base + nf * 8 + gid;
            uint32_t b0 = __float_as_uint(Bb[ks + tig][n0]);
            uint32_t b1 = __float_as_uint(Bb[ks + tig + 4][n0]);
            #pragma unroll
            for (int mf = 0; mf < 4; mf++)
                mma_tf32(acc[mf][nf], a[mf], b0, b1);
        }
    }
}

__device__ __forceinline__ void mma_tile128(
    const float* __restrict__ A, int lda,
    const float* __restrict__ B, int ldb,
    int kLen,
    float (*As)[16][APAD], float (*Bs)[16][BPAD2],
    float (&acc)[4][4][4])
{
    int tid = threadIdx.x;
    int ar = tid >> 1, ac = (tid & 1) * 8;
    int br = tid >> 4, bc = (tid & 15) * 4;
    int lane = tid & 31, wid = tid >> 5;
    int gid = lane >> 2, tig = lane & 3;
    int m_base = (wid & 1) * 64, n_base = (wid >> 1) * 32;

    const float* Ap = A + (size_t)ar * lda + ac;
    const float* Bp = B + (size_t)br * ldb + bc;

    {
        float4 av0 = *(const float4*)(Ap);
        float4 av1 = *(const float4*)(Ap + 4);
        float4 bv0 = *(const float4*)(Bp);
        float4 bv1 = *(const float4*)(Bp + 64);
        As[0][ac + 0][ar] = to_tf32(av0.x); As[0][ac + 1][ar] = to_tf32(av0.y);
        As[0][ac + 2][ar] = to_tf32(av0.z); As[0][ac + 3][ar] = to_tf32(av0.w);
        As[0][ac + 4][ar] = to_tf32(av1.x); As[0][ac + 5][ar] = to_tf32(av1.y);
        As[0][ac + 6][ar] = to_tf32(av1.z); As[0][ac + 7][ar] = to_tf32(av1.w);
        float4 bt0 = make_float4(to_tf32(bv0.x), to_tf32(bv0.y), to_tf32(bv0.z), to_tf32(bv0.w));
        float4 bt1 = make_float4(to_tf32(bv1.x), to_tf32(bv1.y), to_tf32(bv1.z), to_tf32(bv1.w));
        *(float4*)&Bs[0][br][bc]      = bt0;
        *(float4*)&Bs[0][br][bc + 64] = bt1;
    }
    __syncthreads();

    int kc = kLen >> 4;
    for (int c = 1; c < kc; c++) {
        const float* Ac = Ap + c * 16;
        const float* Bc = Bp + (size_t)(c * 16) * ldb;
        float4 av0 = *(const float4*)(Ac);
        float4 av1 = *(const float4*)(Ac + 4);
        float4 bv0 = *(const float4*)(Bc);
        float4 bv1 = *(const float4*)(Bc + 64);
        int pb = (c - 1) & 1, nb = c & 1;
        mma_compute128(As[pb], Bs[pb], m_base, n_base, gid, tig, acc);
        As[nb][ac + 0][ar] = to_tf32(av0.x); As[nb][ac + 1][ar] = to_tf32(av0.y);
        As[nb][ac + 2][ar] = to_tf32(av0.z); As[nb][ac + 3][ar] = to_tf32(av0.w);
        As[nb][ac + 4][ar] = to_tf32(av1.x); As[nb][ac + 5][ar] = to_tf32(av1.y);
        As[nb][ac + 6][ar] = to_tf32(av1.z); As[nb][ac + 7][ar] = to_tf32(av1.w);
        float4 bt0 = make_float4(to_tf32(bv0.x), to_tf32(bv0.y), to_tf32(bv0.z), to_tf32(bv0.w));
        float4 bt1 = make_float4(to_tf32(bv1.x), to_tf32(bv1.y), to_tf32(bv1.z), to_tf32(bv1.w));
        *(float4*)&Bs[nb][br][bc]      = bt0;
        *(float4*)&Bs[nb][br][bc + 64] = bt1;
        __syncthreads();
    }
    int lb = (kc - 1) & 1;
    mma_compute128(As[lb], Bs[lb], m_base, n_base, gid, tig, acc);
}

// ---------------- fused QKV: grid (18,16); blockIdx.x/6 selects matrix ----------------
__global__ void __launch_bounds__(256, 2) qkv_kernel(
    const float* __restrict__ x,
    const float* __restrict__ Wq, const float* __restrict__ Wk, const float* __restrict__ Wv,
    const float* __restrict__ bq, const float* __restrict__ bk, const float* __restrict__ bv,
    float* __restrict__ q, float* __restrict__ k, float* __restrict__ v)
{
    __shared__ float As[2][16][APAD];
    __shared__ float Bs[2][16][BPAD2];
    int sel = blockIdx.x / 6;
    int bn  = (blockIdx.x % 6) * 128;
    int bm  = blockIdx.y * 128;
    const float* B    = sel == 0 ? Wq : (sel == 1 ? Wk : Wv);
    const float* bias = sel == 0 ? bq : (sel == 1 ? bk : bv);
    float* C          = sel == 0 ? q  : (sel == 1 ? k  : v);
    float acc[4][4][4] = {};
    mma_tile128(x + (size_t)bm * HID, HID, B + bn, HID, HID, As, Bs, acc);
    int tid = threadIdx.x, lane = tid & 31, wid = tid >> 5;
    int gid = lane >> 2, tig = lane & 3;
    int m_base = (wid & 1) * 64, n_base = (wid >> 1) * 32;
    #pragma unroll
    for (int mf = 0; mf < 4; mf++) {
        int r0 = bm + m_base + mf * 16 + gid;
        #pragma unroll
        for (int nf = 0; nf < 4; nf++) {
            int col = bn + n_base + nf * 8 + tig * 2;
            float2 bi = *(const float2*)(bias + col);
            *(float2*)(C + (size_t)r0 * HID + col) =
                make_float2(acc[mf][nf][0] + bi.x, acc[mf][nf][1] + bi.y);
            *(float2*)(C + (size_t)(r0 + 8) * HID + col) =
                make_float2(acc[mf][nf][2] + bi.x, acc[mf][nf][3] + bi.y);
        }
    }
}

// ---------------- generic gemm: grid (N/128, M/128); mode 0=+bias 2=gelu(+bias) ----------------
__global__ void __launch_bounds__(256, 2) gemm_kernel(
    const float* __restrict__ A, int K,
    const float* __restrict__ B, int N,
    const float* __restrict__ bias,
    float* __restrict__ C, int mode)
{
    __shared__ float As[2][16][APAD];
    __shared__ float Bs[2][16][BPAD2];
    int bm = blockIdx.y * 128, bn = blockIdx.x * 128;
    float acc[4][4][4] = {};
    mma_tile128(A + (size_t)bm * K, K, B + bn, N, K, As, Bs, acc);
    int tid = threadIdx.x, lane = tid & 31, wid = tid >> 5;
    int gid = lane >> 2, tig = lane & 3;
    int m_base = (wid & 1) * 64, n_base = (wid >> 1) * 32;
    #pragma unroll
    for (int mf = 0; mf < 4; mf++) {
        int r0 = bm + m_base + mf * 16 + gid;
        #pragma unroll
        for (int nf = 0; nf < 4; nf++) {
            int col = bn + n_base + nf * 8 + tig * 2;
            float2 bi = *(const float2*)(bias + col);
            float o0 = acc[mf][nf][0] + bi.x, o1 = acc[mf][nf][1] + bi.y;
            float o2 = acc[mf][nf][2] + bi.x, o3 = acc[mf][nf][3] + bi.y;
            if (mode == 2) { o0 = gelu1(o0); o1 = gelu1(o1); o2 = gelu1(o2); o3 = gelu1(o3); }
            *(float2*)(C + (size_t)r0 * N + col)       = make_float2(o0, o1);
            *(float2*)(C + (size_t)(r0 + 8) * N + col) = make_float2(o2, o3);
        }
    }
}

// ---------------- split-K=4 gemm: grid (N/128, M/128, 4) -> raw partials ----------------
__global__ void __launch_bounds__(256, 2) gemm_split4_kernel(
    const float* __restrict__ A, int K,
    const float* __restrict__ B, int N,
    float* __restrict__ P0, float* __restrict__ P1,
    float* __restrict__ P2, float* __restrict__ P3)
{
    __shared__ float As[2][16][APAD];
    __shared__ float Bs[2][16][BPAD2];
    int bm = blockIdx.y * 128, bn = blockIdx.x * 128;
    int quart = K >> 2, z = blockIdx.z;
    float acc[4][4][4] = {};
    mma_tile128(A + (size_t)bm * K + z * quart, K,
                B + (size_t)(z * quart) * N + bn, N, quart, As, Bs, acc);
    float* C = (z == 0) ? P0 : (z == 1) ? P1 : (z == 2) ? P2 : P3;
    int tid = threadIdx.x, lane = tid & 31, wid = tid >> 5;
    int gid = lane >> 2, tig = lane & 3;
    int m_base = (wid & 1) * 64, n_base = (wid >> 1) * 32;
    #pragma unroll
    for (int mf = 0; mf < 4; mf++) {
        int r0 = bm + m_base + mf * 16 + gid;
        #pragma unroll
        for (int nf = 0; nf < 4; nf++) {
            int col = bn + n_base + nf * 8 + tig * 2;
            *(float2*)(C + (size_t)r0 * N + col)       = make_float2(acc[mf][nf][0], acc[mf][nf][1]);
            *(float2*)(C + (size_t)(r0 + 8) * N + col) = make_float2(acc[mf][nf][2], acc[mf][nf][3]);
        }
    }
}

// ---------------- epilogue: out = p0 + p1 + p2 + p3 + bias + res ----------------
__global__ void epi4_kernel(const float* __restrict__ p0, const float* __restrict__ p1,
                            const float* __restrict__ p2, const float* __restrict__ p3,
                            const float* __restrict__ bias, const float* __restrict__ res,
                            float* __restrict__ out)
{
    int idx = (blockIdx.x * 256 + threadIdx.x) * 4;
    int col = idx % HID;
    float4 a  = *(const float4*)(p0 + idx);
    float4 b  = *(const float4*)(p1 + idx);
    float4 c  = *(const float4*)(p2 + idx);
    float4 d  = *(const float4*)(p3 + idx);
    float4 r  = *(const float4*)(res + idx);
    float4 bi = *(const float4*)(bias + col);
    float4 o = make_float4(a.x + b.x + c.x + d.x + r.x + bi.x,
                           a.y + b.y + c.y + d.y + r.y + bi.y,
                           a.z + b.z + c.z + d.z + r.z + bi.z,
                           a.w + b.w + c.w + d.w + r.w + bi.w);
    *(float4*)(out + idx) = o;
}

// ---------------- L1 distance -> exp(score) + per-tile row sums ----------------
// Scores always <= 0, |score| << 87 -> exp without max-subtraction is exact.
__global__ void __launch_bounds__(256, 2) dist_kernel(
    const float* __restrict__ Q, const float* __restrict__ Km,
    const float* __restrict__ lamp, float* __restrict__ attn,
    float* __restrict__ pS)
{
    __shared__ unsigned long long Qs[32][128];   // [d-pair][q-row]
    __shared__ unsigned long long Ks[32][64];    // negated K
    int bh = blockIdx.z, b = bh / NHEAD, h = bh - b * NHEAD;
    int qbase = blockIdx.y * 128, kbase = blockIdx.x * 64;
    const float* Qb = Q  + (size_t)b * SEQ * HID + h * HDIM + (size_t)qbase * HID;
    const float* Kb = Km + (size_t)b * SEQ * HID + h * HDIM + (size_t)kbase * HID;
    int tid = threadIdx.x;

    union F2U { float2 f; unsigned long long u; };
    {
        int row = tid >> 1, hh = (tid & 1) * 32;
        #pragma unroll
        for (int i = 0; i < 8; i++) {
            float4 qv = *(const float4*)(Qb + (size_t)row * HID + hh + i * 4);
            F2U t;
            t.f = make_float2(qv.x, qv.y); Qs[(hh >> 1) + i * 2][row]     = t.u;
            t.f = make_float2(qv.z, qv.w); Qs[(hh >> 1) + i * 2 + 1][row] = t.u;
        }
    }
    {
        int row = tid >> 2, kq = (tid & 3) * 16;
        #pragma unroll
        for (int i = 0; i < 4; i++) {
            float4 kv = *(const float4*)(Kb + (size_t)row * HID + kq + i * 4);
            F2U t;
            t.f = make_float2(-kv.x, -kv.y); Ks[(kq >> 1) + i * 2][row]     = t.u;
            t.f = make_float2(-kv.z, -kv.w); Ks[(kq >> 1) + i * 2 + 1][row] = t.u;
        }
    }
    __syncthreads();

    int tx = tid & 15, ty = tid >> 4;
    int qs = ty * 8, ks = tx * 4;
    unsigned long long acc[8][4] = {};
    const unsigned long long MASK = 0x7FFFFFFF7FFFFFFFull;
    #pragma unroll 8
    for (int d = 0; d < 32; d++) {
        unsigned long long qv[8], kv[4];
        *(ulonglong2*)&qv[0] = *(const ulonglong2*)&Qs[d][qs];
        *(ulonglong2*)&qv[2] = *(const ulonglong2*)&Qs[d][qs + 2];
        *(ulonglong2*)&qv[4] = *(const ulonglong2*)&Qs[d][qs + 4];
        *(ulonglong2*)&qv[6] = *(const ulonglong2*)&Qs[d][qs + 6];
        *(ulonglong2*)&kv[0] = *(const ulonglong2*)&Ks[d][ks];
        *(ulonglong2*)&kv[2] = *(const ulonglong2*)&Ks[d][ks + 2];
        #pragma unroll
        for (int i = 0; i < 8; i++)
            #pragma unroll
            for (int j = 0; j < 4; j++) {
                unsigned long long df = f2add(qv[i], kv[j]) & MASK;
                acc[i][j] = f2add(acc[i][j], df);
            }
    }
    float c = -(*lamp) * 0.125f;   // scale = 1/sqrt(64)
    float* outp = attn + (size_t)bh * SEQ * SEQ + (size_t)(qbase + qs) * SEQ + kbase + ks;
    size_t srow = ((size_t)bh * SEQ + qbase + qs) * 16 + blockIdx.x;
    #pragma unroll
    for (int i = 0; i < 8; i++) {
        F2U t;
        float e0, e1, e2, e3;
        t.u = acc[i][0]; e0 = __expf(c * (t.f.x + t.f.y));
        t.u = acc[i][1]; e1 = __expf(c * (t.f.x + t.f.y));
        t.u = acc[i][2]; e2 = __expf(c * (t.f.x + t.f.y));
        t.u = acc[i][3]; e3 = __expf(c * (t.f.x + t.f.y));
        *(float4*)(outp + (size_t)i * SEQ) = make_float4(e0, e1, e2, e3);
        float s = e0 + e1 + e2 + e3;
        #pragma unroll
        for (int o = 8; o; o >>= 1) s += __shfl_xor_sync(0xffffffffu, s, o);
        if (tx == 0) pS[srow + (size_t)i * 16] = s;
    }
}

// ---------------- fused stats-fold + normalize + attn write + attn@V ----------------
// BM=64 tile -> grid (16,1,24)=384 blocks (best measured pv config).
__global__ void __launch_bounds__(256, 4) pv_kernel(
    float* __restrict__ attn, const float* __restrict__ V,
    const float* __restrict__ pS, float* __restrict__ O)
{
    __shared__ float As[2][16][APD64];
    __shared__ float Bs[2][16][BPAD];
    __shared__ float smI[64];
    int bh = blockIdx.z, b = bh / NHEAD, h = bh - b * NHEAD;
    int bm = blockIdx.x * 64;
    float* A        = attn + (size_t)bh * SEQ * SEQ + (size_t)bm * SEQ;
    const float* Bv = V + (size_t)b * SEQ * HID + h * HDIM;
    int tid = threadIdx.x;
    if (tid < 64) {
        const float* s16 = pS + ((size_t)bh * SEQ + bm + tid) * 16;
        float s = 0.f;
        #pragma unroll
        for (int j = 0; j < 16; j += 4) {
            float4 a4 = *(const float4*)(s16 + j);
            s += a4.x + a4.y + a4.z + a4.w;
        }
        smI[tid] = 1.f / s;
    }
    __syncthreads();

    int ar = tid >> 2, ac = (tid & 3) * 4;       // A: 64 rows x 16 cols, 4 floats/thread
    int br = tid >> 4, bc = (tid & 15) * 4;      // V: 16 rows x 64 cols
    int lane = tid & 31, wid = tid >> 5;
    int gid = lane >> 2, tig = lane & 3;
    int m_base = (wid & 1) * 32, n_base = (wid >> 1) * 16;
    float rowI = smI[ar];
    float acc[2][2][4] = {};

    float* Ap       = A + (size_t)ar * SEQ + ac;
    const float* Bp = Bv + (size_t)br * HID + bc;

    {   // chunk 0: load exp, normalize (FMUL), write back, stage tf32
        float4 a0 = *(const float4*)(Ap);
        float4 bv = *(const float4*)(Bp);
        float n0 = a0.x * rowI, n1 = a0.y * rowI, n2 = a0.z * rowI, n3 = a0.w * rowI;
        *(float4*)(Ap) = make_float4(n0, n1, n2, n3);
        As[0][ac + 0][ar] = to_tf32(n0); As[0][ac + 1][ar] = to_tf32(n1);
        As[0][ac + 2][ar] = to_tf32(n2); As[0][ac + 3][ar] = to_tf32(n3);
        float4 bt = make_float4(to_tf32(bv.x), to_tf32(bv.y), to_tf32(bv.z), to_tf32(bv.w));
        *(float4*)&Bs[0][br][bc] = bt;
    }
    __syncthreads();

    for (int c = 1; c < SEQ / 16; c++) {
        float* Ac = Ap + c * 16;
        float4 a0 = *(const float4*)(Ac);
        float4 bv = *(const float4*)(Bp + (size_t)(c * 16) * HID);
        int pb = (c - 1) & 1, nb = c & 1;
        #pragma unroll
        for (int ks = 0; ks < 16; ks += 8) {
            uint32_t a[2][4];
            #pragma unroll
            for (int mf = 0; mf < 2; mf++) {
                int m0 = m_base + mf * 16 + gid;
                a[mf][0] = __float_as_uint(As[pb][ks + tig][m0]);
                a[mf][1] = __float_as_uint(As[pb][ks + tig][m0 + 8]);
                a[mf][2] = __float_as_uint(As[pb][ks + tig + 4][m0]);
                a[mf][3] = __float_as_uint(As[pb][ks + tig + 4][m0 + 8]);
            }
            #pragma unroll
            for (int nf = 0; nf < 2; nf++) {
                int n0 = n_base + nf * 8 + gid;
                uint32_t b0 = __float_as_uint(Bs[pb][ks + tig][n0]);
                uint32_t b1 = __float_as_uint(Bs[pb][ks + tig + 4][n0]);
                mma_tf32(acc[0][nf], a[0], b0, b1);
                mma_tf32(acc[1][nf], a[1], b0, b1);
            }
        }
        float n0 = a0.x * rowI, n1 = a0.y * rowI, n2 = a0.z * rowI, n3 = a0.w * rowI;
        *(float4*)(Ac) = make_float4(n0, n1, n2, n3);
        As[nb][ac + 0][ar] = to_tf32(n0); As[nb][ac + 1][ar] = to_tf32(n1);
        As[nb][ac + 2][ar] = to_tf32(n2); As[nb][ac + 3][ar] = to_tf32(n3);
        float4 bt = make_float4(to_tf32(bv.x), to_tf32(bv.y), to_tf32(bv.z), to_tf32(bv.w));
        *(float4*)&Bs[nb][br][bc] = bt;
        __syncthreads();
    }
    {   // last chunk compute
        int lb = (SEQ / 16 - 1) & 1;
        #pragma unroll
        for (int ks = 0; ks < 16; ks += 8) {
            uint32_t a[2][4];
            #pragma unroll
            for (int mf = 0; mf < 2; mf++) {
                int m0 = m_base + mf * 16 + gid;
                a[mf][0] = __float_as_uint(As[lb][ks + tig][m0]);
                a[mf][1] = __float_as_uint(As[lb][ks + tig][m0 + 8]);
                a[mf][2] = __float_as_uint(As[lb][ks + tig + 4][m0]);
                a[mf][3] = __float_as_uint(As[lb][ks + tig + 4][m0 + 8]);
            }
            #pragma unroll
            for (int nf = 0; nf < 2; nf++) {
                int n0 = n_base + nf * 8 + gid;
                uint32_t b0 = __float_as_uint(Bs[lb][ks + tig][n0]);
                uint32_t b1 = __float_as_uint(Bs[lb][ks + tig + 4][n0]);
                mma_tf32(acc[0][nf], a[0], b0, b1);
                mma_tf32(acc[1][nf], a[1], b0, b1);
            }
        }
    }

    float* Ob = O + (size_t)b * SEQ * HID + h * HDIM + (size_t)bm * HID;
    #pragma unroll
    for (int mf = 0; mf < 2; mf++) {
        int r0 = m_base + mf * 16 + gid;
        #pragma unroll
        for (int nf = 0; nf < 2; nf++) {
            int col = n_base + nf * 8 + tig * 2;
            *(float2*)(Ob + (size_t)r0 * HID + col)       = make_float2(acc[mf][nf][0], acc[mf][nf][1]);
            *(float2*)(Ob + (size_t)(r0 + 8) * HID + col) = make_float2(acc[mf][nf][2], acc[mf][nf][3]);
        }
    }
}

// ---------------- launch ----------------
extern "C" void kernel_launch(void* const* d_in, const int* in_sizes, int n_in,
                              void* d_out, int out_size) {
    const float* hidden = (const float*)d_in[0];
    const float* ln1g = (const float*)d_in[1];
    const float* ln1b = (const float*)d_in[2];
    const float* Wq = (const float*)d_in[3];
    const float* bq = (const float*)d_in[4];
    const float* Wk = (const float*)d_in[5];
    const float* bk = (const float*)d_in[6];
    const float* Wv = (const float*)d_in[7];
    const float* bv = (const float*)d_in[8];
    const float* Wo = (const float*)d_in[9];
    const float* bo = (const float*)d_in[10];
    const float* lam = (const float*)d_in[11];
    const float* ln2g = (const float*)d_in[12];
    const float* ln2b = (const float*)d_in[13];
    const float* W1 = (const float*)d_in[14];
    const float* b1 = (const float*)d_in[15];
    const float* W2 = (const float*)d_in[16];
    const float* b2 = (const float*)d_in[17];

    float* out0 = (float*)d_out;
    float* attn = out0 + (size_t)MTOT * HID;  // [B,NH,S,S] follows [B,S,H]

    float *x, *q, *k, *v, *ao, *r1, *y, *ff;
    cudaGetSymbolAddress((void**)&x,  g_x);
    cudaGetSymbolAddress((void**)&q,  g_q);
    cudaGetSymbolAddress((void**)&k,  g_k);
    cudaGetSymbolAddress((void**)&v,  g_v);
    cudaGetSymbolAddress((void**)&ao, g_ao);
    cudaGetSymbolAddress((void**)&r1, g_r1);
    cudaGetSymbolAddress((void**)&y,  g_y);
    cudaGetSymbolAddress((void**)&ff, g_ff);

    float* pS = y + PS_OFF;

    int epiGrid = (MTOT * HID) / (256 * 4);   // 1536

    ln_kernel<<<MTOT, 256>>>(hidden, ln1g, ln1b, x);
    qkv_kernel<<<dim3(18, 16), 256>>>(x, Wq, Wk, Wv, bq, bk, bv, q, k, v);
    dist_kernel<<<dim3(SEQ / 64, SEQ / 128, BHTOT), 256>>>(q, k, lam, attn, pS);
    pv_kernel<<<dim3(SEQ / 64, 1, BHTOT), 256>>>(attn, v, pS, ao);
    // Wo with split-K=4: partials in x, q, k, ff (all dead here; ff consumed before FF1 writes it)
    gemm_split4_kernel<<<dim3(6, 16, 4), 256>>>(ao, HID, Wo, HID, x, q, k, ff);
    epi4_kernel<<<epiGrid, 256>>>(x, q, k, ff, bo, hidden, r1);
    ln_kernel<<<MTOT, 256>>>(r1, ln2g, ln2b, y);   // overwrites pS (already consumed)
    gemm_kernel<<<dim3(24, 16), 256>>>(y, HID, W1, FFD, b1, ff, 2);          // gelu (N=3072)
    // FF2 with split-K=4: partials in x, q, k, v (all dead now)
    gemm_split4_kernel<<<dim3(6, 16, 4), 256>>>(ff, FFD, W2, HID, x, q, k, v);
    epi4_kernel<<<epiGrid, 256>>>(x, q, k, v, b2, r1, out0);
}